// round 1
// baseline (speedup 1.0000x reference)
#include <cuda_runtime.h>
#include <math.h>

#define B_   2
#define S_   2048
#define H_   2048
#define NH_  32
#define NKV_ 8
#define DH_  64
#define M_   (B_*S_)   // 4096 rows

// ---------------------------------------------------------------------------
// Scratch (static device globals; no runtime allocation)
// ---------------------------------------------------------------------------
__device__ float g_q[(size_t)M_ * NH_ * DH_];    // (b,s,h,d)  = (b,s, h*64+d)
__device__ float g_k[(size_t)M_ * NKV_ * DH_];
__device__ float g_v[(size_t)M_ * NKV_ * DH_];
__device__ float g_o[(size_t)M_ * NH_ * DH_];
__device__ float g_invfreq[DH_ / 2];

// ---------------------------------------------------------------------------
// inv_freq init (32 threads, double pow for correctly-rounded fp32 values)
// ---------------------------------------------------------------------------
__global__ void invfreq_init_kernel() {
    int i = threadIdx.x;
    if (i < DH_ / 2) {
        g_invfreq[i] = (float)(1.0 / pow(10000.0, (double)(2 * i) / (double)DH_));
    }
}

// ---------------------------------------------------------------------------
// SGEMM: C[M,N] = A[M,K] @ W[K,N], row-major. BM=BN=128, BK=8, 256 thr, 8x8.
// Requires M%128==0, N%128==0, K%8==0 (true for all our shapes).
// ---------------------------------------------------------------------------
__global__ __launch_bounds__(256) void sgemm128(const float* __restrict__ A,
                                                const float* __restrict__ W,
                                                float* __restrict__ C,
                                                int M, int N, int K)
{
    __shared__ float As[8][132];   // transposed A tile, padded vs bank conflicts
    __shared__ float Bs[8][128];

    const int tid = threadIdx.x;
    const int tx  = tid & 15;
    const int ty  = tid >> 4;
    const int row0 = blockIdx.y * 128;
    const int col0 = blockIdx.x * 128;

    const int ar = tid >> 1;          // 0..127
    const int ac = (tid & 1) * 4;     // 0 or 4
    const int br = tid >> 5;          // 0..7
    const int bc = (tid & 31) * 4;    // 0..124

    const float* Aptr = A + (long)(row0 + ar) * K + ac;
    const float* Bptr = W + (long)br * N + col0 + bc;

    float acc[8][8];
    #pragma unroll
    for (int i = 0; i < 8; i++)
        #pragma unroll
        for (int j = 0; j < 8; j++) acc[i][j] = 0.f;

    for (int k0 = 0; k0 < K; k0 += 8) {
        float4 av = *(const float4*)Aptr;
        float4 bv = *(const float4*)Bptr;
        Aptr += 8;
        Bptr += (long)8 * N;

        __syncthreads();
        As[ac + 0][ar] = av.x;
        As[ac + 1][ar] = av.y;
        As[ac + 2][ar] = av.z;
        As[ac + 3][ar] = av.w;
        *(float4*)&Bs[br][bc] = bv;
        __syncthreads();

        #pragma unroll
        for (int k = 0; k < 8; k++) {
            float4 a0 = *(const float4*)&As[k][ty * 4];
            float4 a1 = *(const float4*)&As[k][64 + ty * 4];
            float4 b0 = *(const float4*)&Bs[k][tx * 4];
            float4 b1 = *(const float4*)&Bs[k][64 + tx * 4];
            float ra[8] = {a0.x, a0.y, a0.z, a0.w, a1.x, a1.y, a1.z, a1.w};
            float rb[8] = {b0.x, b0.y, b0.z, b0.w, b1.x, b1.y, b1.z, b1.w};
            #pragma unroll
            for (int i = 0; i < 8; i++)
                #pragma unroll
                for (int j = 0; j < 8; j++)
                    acc[i][j] += ra[i] * rb[j];
        }
    }

    #pragma unroll
    for (int i = 0; i < 8; i++) {
        int r = row0 + ((i < 4) ? (ty * 4 + i) : (64 + ty * 4 + (i - 4)));
        float4 v0 = make_float4(acc[i][0], acc[i][1], acc[i][2], acc[i][3]);
        float4 v1 = make_float4(acc[i][4], acc[i][5], acc[i][6], acc[i][7]);
        *(float4*)&C[(long)r * N + col0 + tx * 4]      = v0;
        *(float4*)&C[(long)r * N + col0 + 64 + tx * 4] = v1;
    }
}

// ---------------------------------------------------------------------------
// RoPE in-place on g_q and g_k. One thread per (b,s,head,freq-pair).
// ---------------------------------------------------------------------------
__global__ __launch_bounds__(256) void rope_kernel(const int* __restrict__ pos_ids)
{
    const int TOT = M_ * (NH_ + NKV_) * (DH_ / 2);
    int t = blockIdx.x * blockDim.x + threadIdx.x;
    if (t >= TOT) return;

    int i  = t & 31;                     // freq index 0..31
    int h  = (t >> 5) % (NH_ + NKV_);    // 0..39
    int bs = t / (32 * (NH_ + NKV_));    // 0..4095

    float pos = (float)pos_ids[bs];
    float f = pos * g_invfreq[i];
    float sn, c;
    sincosf(f, &sn, &c);

    float* base;
    if (h < NH_) base = g_q + ((long)bs * NH_ + h) * DH_;
    else         base = g_k + ((long)bs * NKV_ + (h - NH_)) * DH_;

    float x1 = base[i];
    float x2 = base[i + 32];
    base[i]      = x1 * c - x2 * sn;
    base[i + 32] = x2 * c + x1 * sn;
}

// ---------------------------------------------------------------------------
// Flash attention: grid (S/64, NH, B), 256 threads, online softmax, fp32.
// 64x64 Q/K/V tiles; thread (tx,ty) owns a 4x4 microtile.
// ---------------------------------------------------------------------------
#define SMPAD 68
#define FLASH_SMEM (4 * 64 * SMPAD * (int)sizeof(float))

__global__ __launch_bounds__(256) void flash_kernel()
{
    extern __shared__ float sm[];
    float* Qs = sm;                 // [d][r]  64 x 68
    float* Ks = sm + 64 * SMPAD;    // [d][c]
    float* Vs = sm + 2 * 64 * SMPAD;// [c][d]
    float* Ps = sm + 3 * 64 * SMPAD;// [c][r]

    const int tid = threadIdx.x;
    const int tx  = tid & 15;
    const int ty  = tid >> 4;
    const int jq  = blockIdx.x;     // q tile index
    const int h   = blockIdx.y;
    const int b   = blockIdx.z;
    const int kvh = h >> 2;         // N_REP = 4
    const int q0  = jq * 64;

    // ---- load Q tile (transposed into [d][r]) ----
    {
        int r  = tid >> 2;
        int d0 = (tid & 3) * 16;
        const float* src = g_q + (((long)b * S_ + q0 + r) * NH_ + h) * DH_ + d0;
        #pragma unroll
        for (int dd = 0; dd < 4; dd++) {
            float4 v = *(const float4*)(src + dd * 4);
            int d = d0 + dd * 4;
            Qs[(d + 0) * SMPAD + r] = v.x;
            Qs[(d + 1) * SMPAD + r] = v.y;
            Qs[(d + 2) * SMPAD + r] = v.z;
            Qs[(d + 3) * SMPAD + r] = v.w;
        }
    }

    float m[4], l[4], accO[4][4];
    #pragma unroll
    for (int i = 0; i < 4; i++) {
        m[i] = -1e30f; l[i] = 0.f;
        #pragma unroll
        for (int j = 0; j < 4; j++) accO[i][j] = 0.f;
    }

    for (int jt = 0; jt <= jq; jt++) {
        __syncthreads();   // previous PV done (and Q visible on first iter)
        // ---- load K (transposed [d][c]) and V ([c][d]) ----
        {
            int c  = tid >> 2;
            int d0 = (tid & 3) * 16;
            long krow = (long)b * S_ + jt * 64 + c;
            const float* ksrc = g_k + (krow * NKV_ + kvh) * DH_ + d0;
            const float* vsrc = g_v + (krow * NKV_ + kvh) * DH_ + d0;
            #pragma unroll
            for (int dd = 0; dd < 4; dd++) {
                int d = d0 + dd * 4;
                float4 k4 = *(const float4*)(ksrc + dd * 4);
                Ks[(d + 0) * SMPAD + c] = k4.x;
                Ks[(d + 1) * SMPAD + c] = k4.y;
                Ks[(d + 2) * SMPAD + c] = k4.z;
                Ks[(d + 3) * SMPAD + c] = k4.w;
                float4 v4 = *(const float4*)(vsrc + dd * 4);
                *(float4*)&Vs[c * SMPAD + d] = v4;
            }
        }
        __syncthreads();

        // ---- S = Q K^T ----
        float s4[4][4];
        #pragma unroll
        for (int i = 0; i < 4; i++)
            #pragma unroll
            for (int j = 0; j < 4; j++) s4[i][j] = 0.f;

        #pragma unroll 16
        for (int d = 0; d < 64; d++) {
            float4 qa = *(const float4*)&Qs[d * SMPAD + ty * 4];
            float4 kb = *(const float4*)&Ks[d * SMPAD + tx * 4];
            float ra[4] = {qa.x, qa.y, qa.z, qa.w};
            float rb[4] = {kb.x, kb.y, kb.z, kb.w};
            #pragma unroll
            for (int i = 0; i < 4; i++)
                #pragma unroll
                for (int j = 0; j < 4; j++)
                    s4[i][j] += ra[i] * rb[j];
        }

        const float scale = 0.125f;  // 1/sqrt(64)
        if (jt == jq) {
            #pragma unroll
            for (int i = 0; i < 4; i++)
                #pragma unroll
                for (int j = 0; j < 4; j++)
                    s4[i][j] = (tx * 4 + j > ty * 4 + i) ? -1e30f : s4[i][j] * scale;
        } else {
            #pragma unroll
            for (int i = 0; i < 4; i++)
                #pragma unroll
                for (int j = 0; j < 4; j++) s4[i][j] *= scale;
        }

        // ---- online softmax update ----
        #pragma unroll
        for (int i = 0; i < 4; i++) {
            float rm = fmaxf(fmaxf(s4[i][0], s4[i][1]), fmaxf(s4[i][2], s4[i][3]));
            rm = fmaxf(rm, __shfl_xor_sync(0xffffffffu, rm, 1, 16));
            rm = fmaxf(rm, __shfl_xor_sync(0xffffffffu, rm, 2, 16));
            rm = fmaxf(rm, __shfl_xor_sync(0xffffffffu, rm, 4, 16));
            rm = fmaxf(rm, __shfl_xor_sync(0xffffffffu, rm, 8, 16));
            float mn    = fmaxf(m[i], rm);
            float alpha = __expf(m[i] - mn);
            m[i] = mn;
            float rs = 0.f;
            #pragma unroll
            for (int j = 0; j < 4; j++) {
                float p = __expf(s4[i][j] - mn);
                s4[i][j] = p;
                rs += p;
            }
            rs += __shfl_xor_sync(0xffffffffu, rs, 1, 16);
            rs += __shfl_xor_sync(0xffffffffu, rs, 2, 16);
            rs += __shfl_xor_sync(0xffffffffu, rs, 4, 16);
            rs += __shfl_xor_sync(0xffffffffu, rs, 8, 16);
            l[i] = l[i] * alpha + rs;
            #pragma unroll
            for (int j = 0; j < 4; j++) accO[i][j] *= alpha;
        }

        // ---- P to smem (transposed [c][r]) ----
        #pragma unroll
        for (int i = 0; i < 4; i++)
            #pragma unroll
            for (int j = 0; j < 4; j++)
                Ps[(tx * 4 + j) * SMPAD + ty * 4 + i] = s4[i][j];
        __syncthreads();

        // ---- O += P V ----
        #pragma unroll 16
        for (int k = 0; k < 64; k++) {
            float4 pp = *(const float4*)&Ps[k * SMPAD + ty * 4];
            float4 vv = *(const float4*)&Vs[k * SMPAD + tx * 4];
            float rp[4] = {pp.x, pp.y, pp.z, pp.w};
            float rv[4] = {vv.x, vv.y, vv.z, vv.w};
            #pragma unroll
            for (int i = 0; i < 4; i++)
                #pragma unroll
                for (int j = 0; j < 4; j++)
                    accO[i][j] += rp[i] * rv[j];
        }
    }

    // ---- epilogue: O / l ----
    #pragma unroll
    for (int i = 0; i < 4; i++) {
        float inv = 1.f / l[i];
        long r = (long)b * S_ + q0 + ty * 4 + i;
        float* dst = g_o + (r * NH_ + h) * DH_ + tx * 4;
        float4 o4 = make_float4(accO[i][0] * inv, accO[i][1] * inv,
                                accO[i][2] * inv, accO[i][3] * inv);
        *(float4*)dst = o4;
    }
}

// ---------------------------------------------------------------------------
// launch
// ---------------------------------------------------------------------------
extern "C" void kernel_launch(void* const* d_in, const int* in_sizes, int n_in,
                              void* d_out, int out_size)
{
    const float* X    = (const float*)d_in[0];   // hidden_states (B,S,H)
    const int*   pos  = (const int*)  d_in[1];   // position_ids (B,S)
    const float* Wq   = (const float*)d_in[2];   // (H, NH*DH)
    const float* Wk   = (const float*)d_in[3];   // (H, NKV*DH)
    const float* Wv   = (const float*)d_in[4];   // (H, NKV*DH)
    const float* Wo   = (const float*)d_in[5];   // (NH*DH, H)
    float*       out  = (float*)d_out;           // (B,S,H)

    void *pq, *pk, *pv, *po;
    cudaGetSymbolAddress(&pq, g_q);
    cudaGetSymbolAddress(&pk, g_k);
    cudaGetSymbolAddress(&pv, g_v);
    cudaGetSymbolAddress(&po, g_o);

    cudaFuncSetAttribute(flash_kernel,
                         cudaFuncAttributeMaxDynamicSharedMemorySize, FLASH_SMEM);

    invfreq_init_kernel<<<1, 32>>>();

    // QKV projections
    sgemm128<<<dim3((NH_ * DH_) / 128, M_ / 128), 256>>>(X, Wq, (float*)pq, M_, NH_ * DH_, H_);
    sgemm128<<<dim3((NKV_ * DH_) / 128, M_ / 128), 256>>>(X, Wk, (float*)pk, M_, NKV_ * DH_, H_);
    sgemm128<<<dim3((NKV_ * DH_) / 128, M_ / 128), 256>>>(X, Wv, (float*)pv, M_, NKV_ * DH_, H_);

    // RoPE on q and k
    {
        const int TOT = M_ * (NH_ + NKV_) * (DH_ / 2);
        rope_kernel<<<(TOT + 255) / 256, 256>>>(pos);
    }

    // causal GQA attention
    flash_kernel<<<dim3(S_ / 64, NH_, B_), 256, FLASH_SMEM>>>();

    // output projection
    sgemm128<<<dim3(H_ / 128, M_ / 128), 256>>>((const float*)po, Wo, out, M_, H_, NH_ * DH_);
}

// round 3
// speedup vs baseline: 1.3296x; 1.3296x over previous
#include <cuda_runtime.h>
#include <math.h>

#define B_   2
#define S_   2048
#define H_   2048
#define NH_  32
#define NKV_ 8
#define DH_  64
#define M_   (B_*S_)   // 4096 rows

typedef unsigned long long u64;

// ---------------------------------------------------------------------------
// Scratch (static device globals; no runtime allocation)
// ---------------------------------------------------------------------------
__device__ float g_q[(size_t)M_ * NH_ * DH_];    // row-major M x 2048, col = h*64+d
__device__ float g_k[(size_t)M_ * NKV_ * DH_];   // M x 512
__device__ float g_v[(size_t)M_ * NKV_ * DH_];   // M x 512
__device__ float g_o[(size_t)M_ * NH_ * DH_];    // M x 2048
__device__ float g_invfreq[DH_ / 2];

// ---------------------------------------------------------------------------
// packed fp32x2 helpers (sm_100+ packed FMA pipe — 2x scalar FFMA throughput)
// ---------------------------------------------------------------------------
__device__ __forceinline__ u64 pack2(float lo, float hi) {
    u64 r; asm("mov.b64 %0, {%1, %2};" : "=l"(r) : "f"(lo), "f"(hi)); return r;
}
__device__ __forceinline__ void unpack2(u64 v, float& lo, float& hi) {
    asm("mov.b64 {%0, %1}, %2;" : "=f"(lo), "=f"(hi) : "l"(v));
}
__device__ __forceinline__ void fma2(u64& d, u64 a, u64 b) {
    asm("fma.rn.f32x2 %0, %1, %2, %0;" : "+l"(d) : "l"(a), "l"(b));
}
__device__ __forceinline__ u64 mul2(u64 a, u64 b) {
    u64 d; asm("mul.rn.f32x2 %0, %1, %2;" : "=l"(d) : "l"(a), "l"(b)); return d;
}

// ---------------------------------------------------------------------------
// inv_freq init
// ---------------------------------------------------------------------------
__global__ void invfreq_init_kernel() {
    int i = threadIdx.x;
    if (i < DH_ / 2) {
        g_invfreq[i] = (float)(1.0 / pow(10000.0, (double)(2 * i) / (double)DH_));
    }
}

// ---------------------------------------------------------------------------
// Double-buffered SGEMM body: C[M,N](+col0/row0) = A[M,K] @ W[K,N]
// BM=BN=128, BK=16, 256 threads, 8x8 microtile, f32x2 accumulation.
// ---------------------------------------------------------------------------
struct GemmSmem {
    float As[2][16][132];   // [buf][k][row] transposed A tile
    float Bs[2][16][128];   // [buf][k][col]
};

__device__ __forceinline__ void gemm_body(GemmSmem& sm,
    const float* __restrict__ A, const float* __restrict__ W, float* __restrict__ C,
    int N, int K, int row0, int col0)
{
    const int tid = threadIdx.x;
    const int tx  = tid & 15;
    const int ty  = tid >> 4;
    const int ar  = tid >> 1;          // 0..127
    const int ac  = (tid & 1) * 8;     // 0 or 8
    const int br  = tid >> 4;          // 0..15
    const int bc  = (tid & 15) * 8;    // 0..120

    const float* Aptr = A + (size_t)(row0 + ar) * K + ac;
    const float* Bptr = W + (size_t)br * N + col0 + bc;

    u64 acc[8][4];
    #pragma unroll
    for (int i = 0; i < 8; i++)
        #pragma unroll
        for (int j = 0; j < 4; j++) acc[i][j] = 0ull;

    float4 ra0 = *(const float4*)Aptr;
    float4 ra1 = *(const float4*)(Aptr + 4);
    float4 rb0 = *(const float4*)Bptr;
    float4 rb1 = *(const float4*)(Bptr + 4);

    int buf = 0;
    sm.As[0][ac+0][ar] = ra0.x; sm.As[0][ac+1][ar] = ra0.y;
    sm.As[0][ac+2][ar] = ra0.z; sm.As[0][ac+3][ar] = ra0.w;
    sm.As[0][ac+4][ar] = ra1.x; sm.As[0][ac+5][ar] = ra1.y;
    sm.As[0][ac+6][ar] = ra1.z; sm.As[0][ac+7][ar] = ra1.w;
    *(float4*)&sm.Bs[0][br][bc]   = rb0;
    *(float4*)&sm.Bs[0][br][bc+4] = rb1;
    __syncthreads();

    const int nk = K >> 4;
    for (int kt = 0; kt < nk; kt++) {
        const bool more = (kt + 1 < nk);
        if (more) {
            Aptr += 16;
            Bptr += (size_t)16 * N;
            ra0 = *(const float4*)Aptr;
            ra1 = *(const float4*)(Aptr + 4);
            rb0 = *(const float4*)Bptr;
            rb1 = *(const float4*)(Bptr + 4);
        }
        #pragma unroll
        for (int k = 0; k < 16; k++) {
            float4 a0 = *(const float4*)&sm.As[buf][k][ty * 4];
            float4 a1 = *(const float4*)&sm.As[buf][k][64 + ty * 4];
            float4 b0 = *(const float4*)&sm.Bs[buf][k][tx * 4];
            float4 b1 = *(const float4*)&sm.Bs[buf][k][64 + tx * 4];
            u64 b2[4] = { pack2(b0.x, b0.y), pack2(b0.z, b0.w),
                          pack2(b1.x, b1.y), pack2(b1.z, b1.w) };
            float av[8] = {a0.x, a0.y, a0.z, a0.w, a1.x, a1.y, a1.z, a1.w};
            #pragma unroll
            for (int i = 0; i < 8; i++) {
                u64 a2 = pack2(av[i], av[i]);
                #pragma unroll
                for (int j = 0; j < 4; j++) fma2(acc[i][j], a2, b2[j]);
            }
        }
        if (more) {
            sm.As[buf^1][ac+0][ar] = ra0.x; sm.As[buf^1][ac+1][ar] = ra0.y;
            sm.As[buf^1][ac+2][ar] = ra0.z; sm.As[buf^1][ac+3][ar] = ra0.w;
            sm.As[buf^1][ac+4][ar] = ra1.x; sm.As[buf^1][ac+5][ar] = ra1.y;
            sm.As[buf^1][ac+6][ar] = ra1.z; sm.As[buf^1][ac+7][ar] = ra1.w;
            *(float4*)&sm.Bs[buf^1][br][bc]   = rb0;
            *(float4*)&sm.Bs[buf^1][br][bc+4] = rb1;
            __syncthreads();
            buf ^= 1;
        }
    }

    #pragma unroll
    for (int i = 0; i < 8; i++) {
        int r = row0 + ((i < 4) ? (ty * 4 + i) : (64 + ty * 4 + (i - 4)));
        float o[8];
        unpack2(acc[i][0], o[0], o[1]); unpack2(acc[i][1], o[2], o[3]);
        unpack2(acc[i][2], o[4], o[5]); unpack2(acc[i][3], o[6], o[7]);
        *(float4*)&C[(size_t)r * N + col0 + tx * 4]      = make_float4(o[0], o[1], o[2], o[3]);
        *(float4*)&C[(size_t)r * N + col0 + 64 + tx * 4] = make_float4(o[4], o[5], o[6], o[7]);
    }
}

// Fused QKV projection: blockIdx.x 0..15 -> Q cols, 16..19 -> K, 20..23 -> V
__global__ __launch_bounds__(256, 2) void qkv_gemm(const float* __restrict__ X,
    const float* __restrict__ Wq, const float* __restrict__ Wk, const float* __restrict__ Wv)
{
    __shared__ GemmSmem sm;
    const int bx = blockIdx.x;
    const float* W; float* C; int N, col;
    if (bx < 16)      { W = Wq; C = g_q; N = NH_ * DH_;  col = bx * 128; }
    else if (bx < 20) { W = Wk; C = g_k; N = NKV_ * DH_; col = (bx - 16) * 128; }
    else              { W = Wv; C = g_v; N = NKV_ * DH_; col = (bx - 20) * 128; }
    gemm_body(sm, X, W, C, N, H_, blockIdx.y * 128, col);
}

__global__ __launch_bounds__(256, 2) void sgemm_db(const float* __restrict__ A,
    const float* __restrict__ W, float* __restrict__ C, int N, int K)
{
    __shared__ GemmSmem sm;
    gemm_body(sm, A, W, C, N, K, blockIdx.y * 128, blockIdx.x * 128);
}

// ---------------------------------------------------------------------------
// RoPE in-place on g_q and g_k
// ---------------------------------------------------------------------------
__global__ __launch_bounds__(256) void rope_kernel(const int* __restrict__ pos_ids)
{
    const int TOT = M_ * (NH_ + NKV_) * (DH_ / 2);
    int t = blockIdx.x * blockDim.x + threadIdx.x;
    if (t >= TOT) return;

    int i  = t & 31;
    int h  = (t >> 5) % (NH_ + NKV_);
    int bs = t / (32 * (NH_ + NKV_));

    float pos = (float)pos_ids[bs];
    float f = pos * g_invfreq[i];
    float sn, c;
    sincosf(f, &sn, &c);

    float* base;
    if (h < NH_) base = g_q + ((size_t)bs * NH_ + h) * DH_;
    else         base = g_k + ((size_t)bs * NKV_ + (h - NH_)) * DH_;

    float x1 = base[i];
    float x2 = base[i + 32];
    base[i]      = x1 * c - x2 * sn;
    base[i + 32] = x2 * c + x1 * sn;
}

// ---------------------------------------------------------------------------
// Flash attention v2: BM=128 q rows x BN=64 kv cols, 256 thr, 8x4 microtile,
// f32x2 FMA, online softmax. grid (S/128, NH, B).
// ---------------------------------------------------------------------------
#define QPAD 132
#define KPAD 68
#define PPAD 132
#define FL_QS 0
#define FL_KS (64 * QPAD)
#define FL_VS (FL_KS + 64 * KPAD)
#define FL_PS (FL_VS + 64 * KPAD)
#define FL_TOT (FL_PS + 64 * PPAD)
#define FLASH_SMEM (FL_TOT * (int)sizeof(float))

__global__ __launch_bounds__(256) void flash_kernel()
{
    extern __shared__ float sm[];
    float* Qs = sm + FL_QS;   // [d][r] 64 x 132 (r<128)
    float* Ks = sm + FL_KS;   // [d][c] 64 x 68
    float* Vs = sm + FL_VS;   // [c][d] 64 x 68
    float* Ps = sm + FL_PS;   // [c][r] 64 x 132

    const int tid = threadIdx.x;
    const int tx  = tid & 15;
    const int ty  = tid >> 4;
    const int jq  = (gridDim.x - 1) - blockIdx.x;   // heavy tiles launch first
    const int h   = blockIdx.y;
    const int b   = blockIdx.z;
    const int kvh = h >> 2;      // N_REP = 4
    const int q0  = jq * 128;

    // load Q tile transposed
    {
        int r  = tid >> 1;
        int d0 = (tid & 1) * 32;
        const float* src = g_q + (((size_t)b * S_ + q0 + r) * NH_ + h) * DH_ + d0;
        #pragma unroll
        for (int dd = 0; dd < 8; dd++) {
            float4 v = *(const float4*)(src + dd * 4);
            int d = d0 + dd * 4;
            Qs[(d + 0) * QPAD + r] = v.x;
            Qs[(d + 1) * QPAD + r] = v.y;
            Qs[(d + 2) * QPAD + r] = v.z;
            Qs[(d + 3) * QPAD + r] = v.w;
        }
    }

    float m[8], l[8];
    u64 accO[8][2];
    #pragma unroll
    for (int i = 0; i < 8; i++) {
        m[i] = -1e30f; l[i] = 0.f;
        accO[i][0] = 0ull; accO[i][1] = 0ull;
    }

    const int ntiles = 2 * jq + 2;
    for (int jt = 0; jt < ntiles; jt++) {
        __syncthreads();   // prior PV done; Q visible on first iter
        // load K (transposed [d][c]) and V ([c][d])
        {
            int c  = tid >> 2;
            int d0 = (tid & 3) * 16;
            size_t krow = (size_t)b * S_ + (size_t)jt * 64 + c;
            const float* ksrc = g_k + (krow * NKV_ + kvh) * DH_ + d0;
            const float* vsrc = g_v + (krow * NKV_ + kvh) * DH_ + d0;
            #pragma unroll
            for (int dd = 0; dd < 4; dd++) {
                int d = d0 + dd * 4;
                float4 k4 = *(const float4*)(ksrc + dd * 4);
                Ks[(d + 0) * KPAD + c] = k4.x;
                Ks[(d + 1) * KPAD + c] = k4.y;
                Ks[(d + 2) * KPAD + c] = k4.z;
                Ks[(d + 3) * KPAD + c] = k4.w;
                float4 v4 = *(const float4*)(vsrc + dd * 4);
                *(float4*)&Vs[c * KPAD + d] = v4;
            }
        }
        __syncthreads();

        // S = Q K^T (packed)
        u64 s2[8][2];
        #pragma unroll
        for (int i = 0; i < 8; i++) { s2[i][0] = 0ull; s2[i][1] = 0ull; }

        #pragma unroll 8
        for (int d = 0; d < 64; d++) {
            float4 qa0 = *(const float4*)&Qs[d * QPAD + ty * 8];
            float4 qa1 = *(const float4*)&Qs[d * QPAD + ty * 8 + 4];
            float4 kb  = *(const float4*)&Ks[d * KPAD + tx * 4];
            u64 k20 = pack2(kb.x, kb.y);
            u64 k21 = pack2(kb.z, kb.w);
            float qv[8] = {qa0.x, qa0.y, qa0.z, qa0.w, qa1.x, qa1.y, qa1.z, qa1.w};
            #pragma unroll
            for (int i = 0; i < 8; i++) {
                u64 q2 = pack2(qv[i], qv[i]);
                fma2(s2[i][0], q2, k20);
                fma2(s2[i][1], q2, k21);
            }
        }

        // unpack + scale + causal mask
        float s[8][4];
        const float scale = 0.125f;   // 1/sqrt(64)
        const bool need_mask = (jt >= 2 * jq);
        #pragma unroll
        for (int i = 0; i < 8; i++) {
            unpack2(s2[i][0], s[i][0], s[i][1]);
            unpack2(s2[i][1], s[i][2], s[i][3]);
            #pragma unroll
            for (int j = 0; j < 4; j++) {
                float v = s[i][j] * scale;
                if (need_mask && (jt * 64 + tx * 4 + j > q0 + ty * 8 + i)) v = -1e30f;
                s[i][j] = v;
            }
        }

        // online softmax update
        #pragma unroll
        for (int i = 0; i < 8; i++) {
            float rm = fmaxf(fmaxf(s[i][0], s[i][1]), fmaxf(s[i][2], s[i][3]));
            rm = fmaxf(rm, __shfl_xor_sync(0xffffffffu, rm, 1, 16));
            rm = fmaxf(rm, __shfl_xor_sync(0xffffffffu, rm, 2, 16));
            rm = fmaxf(rm, __shfl_xor_sync(0xffffffffu, rm, 4, 16));
            rm = fmaxf(rm, __shfl_xor_sync(0xffffffffu, rm, 8, 16));
            float mn    = fmaxf(m[i], rm);
            float alpha = __expf(m[i] - mn);
            m[i] = mn;
            float rs = 0.f;
            #pragma unroll
            for (int j = 0; j < 4; j++) {
                float p = __expf(s[i][j] - mn);
                s[i][j] = p;
                rs += p;
            }
            rs += __shfl_xor_sync(0xffffffffu, rs, 1, 16);
            rs += __shfl_xor_sync(0xffffffffu, rs, 2, 16);
            rs += __shfl_xor_sync(0xffffffffu, rs, 4, 16);
            rs += __shfl_xor_sync(0xffffffffu, rs, 8, 16);
            l[i] = l[i] * alpha + rs;
            u64 al2 = pack2(alpha, alpha);
            accO[i][0] = mul2(accO[i][0], al2);
            accO[i][1] = mul2(accO[i][1], al2);
        }

        // P to smem (transposed [c][r])
        #pragma unroll
        for (int i = 0; i < 8; i++)
            #pragma unroll
            for (int j = 0; j < 4; j++)
                Ps[(tx * 4 + j) * PPAD + ty * 8 + i] = s[i][j];
        __syncthreads();

        // O += P V (packed)
        #pragma unroll 8
        for (int k = 0; k < 64; k++) {
            float4 pp0 = *(const float4*)&Ps[k * PPAD + ty * 8];
            float4 pp1 = *(const float4*)&Ps[k * PPAD + ty * 8 + 4];
            float4 vv  = *(const float4*)&Vs[k * KPAD + tx * 4];
            u64 v20 = pack2(vv.x, vv.y);
            u64 v21 = pack2(vv.z, vv.w);
            float pv[8] = {pp0.x, pp0.y, pp0.z, pp0.w, pp1.x, pp1.y, pp1.z, pp1.w};
            #pragma unroll
            for (int i = 0; i < 8; i++) {
                u64 p2 = pack2(pv[i], pv[i]);
                fma2(accO[i][0], p2, v20);
                fma2(accO[i][1], p2, v21);
            }
        }
    }

    // epilogue
    #pragma unroll
    for (int i = 0; i < 8; i++) {
        float inv = 1.f / l[i];
        float o0, o1, o2, o3;
        unpack2(accO[i][0], o0, o1);
        unpack2(accO[i][1], o2, o3);
        size_t r = (size_t)b * S_ + q0 + ty * 8 + i;
        *(float4*)&g_o[(r * NH_ + h) * DH_ + tx * 4] =
            make_float4(o0 * inv, o1 * inv, o2 * inv, o3 * inv);
    }
}

// ---------------------------------------------------------------------------
// launch
// ---------------------------------------------------------------------------
extern "C" void kernel_launch(void* const* d_in, const int* in_sizes, int n_in,
                              void* d_out, int out_size)
{
    const float* X   = (const float*)d_in[0];
    const int*   pos = (const int*)  d_in[1];
    const float* Wq  = (const float*)d_in[2];
    const float* Wk  = (const float*)d_in[3];
    const float* Wv  = (const float*)d_in[4];
    const float* Wo  = (const float*)d_in[5];
    float*       out = (float*)d_out;

    void* po;
    cudaGetSymbolAddress(&po, g_o);

    cudaFuncSetAttribute(flash_kernel,
                         cudaFuncAttributeMaxDynamicSharedMemorySize, FLASH_SMEM);

    invfreq_init_kernel<<<1, 32>>>();

    // fused QKV projection (768 CTAs)
    qkv_gemm<<<dim3(24, M_ / 128), 256>>>(X, Wq, Wk, Wv);

    // RoPE
    {
        const int TOT = M_ * (NH_ + NKV_) * (DH_ / 2);
        rope_kernel<<<(TOT + 255) / 256, 256>>>(pos);
    }

    // causal GQA attention
    flash_kernel<<<dim3(S_ / 128, NH_, B_), 256, FLASH_SMEM>>>();

    // output projection
    sgemm_db<<<dim3(H_ / 128, M_ / 128), 256>>>((const float*)po, Wo, out, H_, NH_ * DH_);
}

// round 7
// speedup vs baseline: 1.5648x; 1.1768x over previous
#include <cuda_runtime.h>
#include <cuda_bf16.h>
#include <math.h>
#include <cstdint>

#define B_   2
#define S_   2048
#define H_   2048
#define NH_  32
#define NKV_ 8
#define DH_  64
#define M_   (B_*S_)      // 4096 rows
#define KP_  6144         // 3*H_ : A'=[hi|hi|lo], W'=[hi|lo|hi]

typedef unsigned long long u64;

// ---------------------------------------------------------------------------
// Scratch (static device globals; no runtime allocation)
// ---------------------------------------------------------------------------
__device__ float g_q[(size_t)M_ * NH_ * DH_];
__device__ float g_k[(size_t)M_ * NKV_ * DH_];
__device__ float g_v[(size_t)M_ * NKV_ * DH_];
__device__ float g_o[(size_t)M_ * NH_ * DH_];
__device__ float g_invfreq[DH_ / 2];

__device__ __align__(128) __nv_bfloat16 g_a2 [(size_t)M_   * KP_];  // X' then O'
__device__ __align__(128) __nv_bfloat16 g_wq2[(size_t)2048 * KP_];  // [N,K'] K-major
__device__ __align__(128) __nv_bfloat16 g_wk2[(size_t)512  * KP_];
__device__ __align__(128) __nv_bfloat16 g_wv2[(size_t)512  * KP_];
__device__ __align__(128) __nv_bfloat16 g_wo2[(size_t)2048 * KP_];

// ---------------------------------------------------------------------------
// helpers
// ---------------------------------------------------------------------------
__device__ __forceinline__ void mma16816(float* d, const uint32_t* a, const uint32_t* b) {
    asm volatile("mma.sync.aligned.m16n8k16.row.col.f32.bf16.bf16.f32 "
                 "{%0,%1,%2,%3}, {%4,%5,%6,%7}, {%8,%9}, {%0,%1,%2,%3};"
                 : "+f"(d[0]), "+f"(d[1]), "+f"(d[2]), "+f"(d[3])
                 : "r"(a[0]), "r"(a[1]), "r"(a[2]), "r"(a[3]), "r"(b[0]), "r"(b[1]));
}

// packed fp32x2 (flash)
__device__ __forceinline__ u64 pack2(float lo, float hi) {
    u64 r; asm("mov.b64 %0, {%1, %2};" : "=l"(r) : "f"(lo), "f"(hi)); return r;
}
__device__ __forceinline__ void unpack2(u64 v, float& lo, float& hi) {
    asm("mov.b64 {%0, %1}, %2;" : "=f"(lo), "=f"(hi) : "l"(v));
}
__device__ __forceinline__ void fma2(u64& d, u64 a, u64 b) {
    asm("fma.rn.f32x2 %0, %1, %2, %0;" : "+l"(d) : "l"(a), "l"(b));
}
__device__ __forceinline__ u64 mul2(u64 a, u64 b) {
    u64 d; asm("mul.rn.f32x2 %0, %1, %2;" : "=l"(d) : "l"(a), "l"(b)); return d;
}

// ---------------------------------------------------------------------------
// inv_freq init
// ---------------------------------------------------------------------------
__global__ void invfreq_init_kernel() {
    int i = threadIdx.x;
    if (i < DH_ / 2) {
        g_invfreq[i] = (float)(1.0 / pow(10000.0, (double)(2 * i) / (double)DH_));
    }
}

// ---------------------------------------------------------------------------
// hi/hi/lo split: src fp32 [4096, 2048] -> dst bf16 [4096, 6144]
// ---------------------------------------------------------------------------
__global__ __launch_bounds__(256) void cvt_hihilo(const float* __restrict__ src,
                                                  __nv_bfloat16* __restrict__ dst)
{
    int t = blockIdx.x * blockDim.x + threadIdx.x;
    int m  = t >> 9;
    int c4 = (t & 511) * 4;
    float4 x = *(const float4*)(src + (size_t)m * 2048 + c4);

    __nv_bfloat16 h0 = __float2bfloat16_rn(x.x), h1 = __float2bfloat16_rn(x.y);
    __nv_bfloat16 h2 = __float2bfloat16_rn(x.z), h3 = __float2bfloat16_rn(x.w);
    __nv_bfloat16 l0 = __float2bfloat16_rn(x.x - __bfloat162float(h0));
    __nv_bfloat16 l1 = __float2bfloat16_rn(x.y - __bfloat162float(h1));
    __nv_bfloat16 l2 = __float2bfloat16_rn(x.z - __bfloat162float(h2));
    __nv_bfloat16 l3 = __float2bfloat16_rn(x.w - __bfloat162float(h3));

    __nv_bfloat162 H01 = __halves2bfloat162(h0, h1), H23 = __halves2bfloat162(h2, h3);
    __nv_bfloat162 L01 = __halves2bfloat162(l0, l1), L23 = __halves2bfloat162(l2, l3);
    uint2 Hv = make_uint2(*(uint32_t*)&H01, *(uint32_t*)&H23);
    uint2 Lv = make_uint2(*(uint32_t*)&L01, *(uint32_t*)&L23);

    size_t base = (size_t)m * KP_ + c4;
    *(uint2*)(dst + base)        = Hv;
    *(uint2*)(dst + base + 2048) = Hv;
    *(uint2*)(dst + base + 4096) = Lv;
}

// ---------------------------------------------------------------------------
// Weight transpose + split: W fp32 [2048, Nout] -> W' bf16 [Nout, 6144]
// seg0 = hi, seg1 = lo, seg2 = hi
// ---------------------------------------------------------------------------
__global__ __launch_bounds__(256) void cvt_w_T(const float* __restrict__ W,
                                               __nv_bfloat16* __restrict__ Wp, int Nout)
{
    __shared__ float tile[32][33];
    int tx = threadIdx.x, ty = threadIdx.y;
    int n0 = blockIdx.x * 32, k0 = blockIdx.y * 32;

    #pragma unroll
    for (int r = 0; r < 4; r++)
        tile[ty + r * 8][tx] = W[(size_t)(k0 + ty + r * 8) * Nout + n0 + tx];
    __syncthreads();

    #pragma unroll
    for (int r = 0; r < 4; r++) {
        int nl = ty + r * 8, kl = tx;
        float v = tile[kl][nl];
        __nv_bfloat16 h = __float2bfloat16_rn(v);
        __nv_bfloat16 l = __float2bfloat16_rn(v - __bfloat162float(h));
        size_t rowb = (size_t)(n0 + nl) * KP_;
        Wp[rowb + k0 + kl]        = h;
        Wp[rowb + 2048 + k0 + kl] = l;
        Wp[rowb + 4096 + k0 + kl] = h;
    }
}

// ---------------------------------------------------------------------------
// bf16 mma.sync GEMM: 128x128 CTA tile, 8 warps (2x4), warp tile 64x32.
// K-slab 32, single smem buffer; direct LDS.32 fragment loads (m16n8k16 spec).
// ---------------------------------------------------------------------------
#define KSLAB 32
#define NSLAB (KP_ / KSLAB)     // 192
#define ARS   40                // smem row stride in bf16 (80 B, 16B-aligned)

__device__ __forceinline__ void mma_gemm_body(
    const __nv_bfloat16* __restrict__ A2, const __nv_bfloat16* __restrict__ W2,
    float* __restrict__ C, int Nout, int row0, int col0)
{
    __shared__ __nv_bfloat16 As[128][ARS];
    __shared__ __nv_bfloat16 Bs[128][ARS];

    const int tid  = threadIdx.x;
    const int lane = tid & 31;
    const int wid  = tid >> 5;
    const int wm   = wid >> 2;      // 0..1  (64-row half)
    const int wn   = wid & 3;       // 0..3  (32-col quarter)
    const int g    = lane >> 2;     // 0..7
    const int tq   = lane & 3;      // 0..3

    const int lrow = tid >> 2;
    const int lk   = (tid & 3) * 8;

    const __nv_bfloat16* Ag = A2 + (size_t)(row0 + lrow) * KP_ + lk;
    const __nv_bfloat16* Bg = W2 + (size_t)(col0 + lrow) * KP_ + lk;

    float acc[4][4][4];
    #pragma unroll
    for (int i = 0; i < 4; i++)
        #pragma unroll
        for (int j = 0; j < 4; j++)
            #pragma unroll
            for (int c = 0; c < 4; c++) acc[i][j][c] = 0.f;

    for (int s = 0; s < NSLAB; s++) {
        uint4 a0 = *(const uint4*)(Ag + s * KSLAB);
        uint4 a1 = *(const uint4*)(Ag + s * KSLAB + (size_t)64 * KP_);
        uint4 b0 = *(const uint4*)(Bg + s * KSLAB);
        uint4 b1 = *(const uint4*)(Bg + s * KSLAB + (size_t)64 * KP_);

        __syncthreads();
        *(uint4*)&As[lrow][lk]      = a0;
        *(uint4*)&As[lrow + 64][lk] = a1;
        *(uint4*)&Bs[lrow][lk]      = b0;
        *(uint4*)&Bs[lrow + 64][lk] = b1;
        __syncthreads();

        #pragma unroll
        for (int ks = 0; ks < 2; ks++) {
            const int c0 = tq * 2 + ks * 16;

            uint32_t af[4][4];
            #pragma unroll
            for (int mt = 0; mt < 4; mt++) {
                const int r = wm * 64 + mt * 16 + g;
                af[mt][0] = *(const uint32_t*)&As[r][c0];
                af[mt][1] = *(const uint32_t*)&As[r + 8][c0];
                af[mt][2] = *(const uint32_t*)&As[r][c0 + 8];
                af[mt][3] = *(const uint32_t*)&As[r + 8][c0 + 8];
            }
            uint32_t bf[4][2];
            #pragma unroll
            for (int nt = 0; nt < 4; nt++) {
                const int n = wn * 32 + nt * 8 + g;
                bf[nt][0] = *(const uint32_t*)&Bs[n][c0];
                bf[nt][1] = *(const uint32_t*)&Bs[n][c0 + 8];
            }
            #pragma unroll
            for (int mt = 0; mt < 4; mt++)
                #pragma unroll
                for (int nt = 0; nt < 4; nt++)
                    mma16816(acc[mt][nt], af[mt], bf[nt]);
        }
    }

    #pragma unroll
    for (int mt = 0; mt < 4; mt++) {
        #pragma unroll
        for (int nt = 0; nt < 4; nt++) {
            int row = row0 + wm * 64 + mt * 16 + g;
            int col = col0 + wn * 32 + nt * 8 + tq * 2;
            *(float2*)&C[(size_t)row * Nout + col] =
                make_float2(acc[mt][nt][0], acc[mt][nt][1]);
            *(float2*)&C[(size_t)(row + 8) * Nout + col] =
                make_float2(acc[mt][nt][2], acc[mt][nt][3]);
        }
    }
}

// QKV fused: bx 0..511 Q (16 n-tiles), 512..639 K (4), 640..767 V (4)
__global__ __launch_bounds__(256, 2) void qkv_mma()
{
    const int bx = blockIdx.x;
    if (bx < 512)
        mma_gemm_body(g_a2, g_wq2, g_q, NH_ * DH_, (bx >> 4) * 128, (bx & 15) * 128);
    else if (bx < 640) {
        int t = bx - 512;
        mma_gemm_body(g_a2, g_wk2, g_k, NKV_ * DH_, (t >> 2) * 128, (t & 3) * 128);
    } else {
        int t = bx - 640;
        mma_gemm_body(g_a2, g_wv2, g_v, NKV_ * DH_, (t >> 2) * 128, (t & 3) * 128);
    }
}

__global__ __launch_bounds__(256, 2) void out_mma(float* __restrict__ out)
{
    const int bx = blockIdx.x;
    mma_gemm_body(g_a2, g_wo2, out, H_, (bx >> 4) * 128, (bx & 15) * 128);
}

// ---------------------------------------------------------------------------
// RoPE in-place on g_q and g_k
// ---------------------------------------------------------------------------
__global__ __launch_bounds__(256) void rope_kernel(const int* __restrict__ pos_ids)
{
    const int TOT = M_ * (NH_ + NKV_) * (DH_ / 2);
    int t = blockIdx.x * blockDim.x + threadIdx.x;
    if (t >= TOT) return;

    int i  = t & 31;
    int h  = (t >> 5) % (NH_ + NKV_);
    int bs = t / (32 * (NH_ + NKV_));

    float pos = (float)pos_ids[bs];
    float f = pos * g_invfreq[i];
    float sn, c;
    sincosf(f, &sn, &c);

    float* base;
    if (h < NH_) base = g_q + ((size_t)bs * NH_ + h) * DH_;
    else         base = g_k + ((size_t)bs * NKV_ + (h - NH_)) * DH_;

    float x1 = base[i];
    float x2 = base[i + 32];
    base[i]      = x1 * c - x2 * sn;
    base[i + 32] = x2 * c + x1 * sn;
}

// ---------------------------------------------------------------------------
// Flash attention v2 (unchanged from passing R3 kernel)
// ---------------------------------------------------------------------------
#define QPAD 132
#define KPAD 68
#define PPAD 132
#define FL_QS 0
#define FL_KS (64 * QPAD)
#define FL_VS (FL_KS + 64 * KPAD)
#define FL_PS (FL_VS + 64 * KPAD)
#define FL_TOT (FL_PS + 64 * PPAD)
#define FLASH_SMEM (FL_TOT * (int)sizeof(float))

__global__ __launch_bounds__(256) void flash_kernel()
{
    extern __shared__ float sm[];
    float* Qs = sm + FL_QS;
    float* Ks = sm + FL_KS;
    float* Vs = sm + FL_VS;
    float* Ps = sm + FL_PS;

    const int tid = threadIdx.x;
    const int tx  = tid & 15;
    const int ty  = tid >> 4;
    const int jq  = (gridDim.x - 1) - blockIdx.x;
    const int h   = blockIdx.y;
    const int b   = blockIdx.z;
    const int kvh = h >> 2;
    const int q0  = jq * 128;

    {
        int r  = tid >> 1;
        int d0 = (tid & 1) * 32;
        const float* src = g_q + (((size_t)b * S_ + q0 + r) * NH_ + h) * DH_ + d0;
        #pragma unroll
        for (int dd = 0; dd < 8; dd++) {
            float4 v = *(const float4*)(src + dd * 4);
            int d = d0 + dd * 4;
            Qs[(d + 0) * QPAD + r] = v.x;
            Qs[(d + 1) * QPAD + r] = v.y;
            Qs[(d + 2) * QPAD + r] = v.z;
            Qs[(d + 3) * QPAD + r] = v.w;
        }
    }

    float m[8], l[8];
    u64 accO[8][2];
    #pragma unroll
    for (int i = 0; i < 8; i++) {
        m[i] = -1e30f; l[i] = 0.f;
        accO[i][0] = 0ull; accO[i][1] = 0ull;
    }

    const int ntiles = 2 * jq + 2;
    for (int jt = 0; jt < ntiles; jt++) {
        __syncthreads();
        {
            int c  = tid >> 2;
            int d0 = (tid & 3) * 16;
            size_t krow = (size_t)b * S_ + (size_t)jt * 64 + c;
            const float* ksrc = g_k + (krow * NKV_ + kvh) * DH_ + d0;
            const float* vsrc = g_v + (krow * NKV_ + kvh) * DH_ + d0;
            #pragma unroll
            for (int dd = 0; dd < 4; dd++) {
                int d = d0 + dd * 4;
                float4 k4 = *(const float4*)(ksrc + dd * 4);
                Ks[(d + 0) * KPAD + c] = k4.x;
                Ks[(d + 1) * KPAD + c] = k4.y;
                Ks[(d + 2) * KPAD + c] = k4.z;
                Ks[(d + 3) * KPAD + c] = k4.w;
                float4 v4 = *(const float4*)(vsrc + dd * 4);
                *(float4*)&Vs[c * KPAD + d] = v4;
            }
        }
        __syncthreads();

        u64 s2[8][2];
        #pragma unroll
        for (int i = 0; i < 8; i++) { s2[i][0] = 0ull; s2[i][1] = 0ull; }

        #pragma unroll 8
        for (int d = 0; d < 64; d++) {
            float4 qa0 = *(const float4*)&Qs[d * QPAD + ty * 8];
            float4 qa1 = *(const float4*)&Qs[d * QPAD + ty * 8 + 4];
            float4 kb  = *(const float4*)&Ks[d * KPAD + tx * 4];
            u64 k20 = pack2(kb.x, kb.y);
            u64 k21 = pack2(kb.z, kb.w);
            float qv[8] = {qa0.x, qa0.y, qa0.z, qa0.w, qa1.x, qa1.y, qa1.z, qa1.w};
            #pragma unroll
            for (int i = 0; i < 8; i++) {
                u64 q2 = pack2(qv[i], qv[i]);
                fma2(s2[i][0], q2, k20);
                fma2(s2[i][1], q2, k21);
            }
        }

        float s[8][4];
        const float scale = 0.125f;
        const bool need_mask = (jt >= 2 * jq);
        #pragma unroll
        for (int i = 0; i < 8; i++) {
            unpack2(s2[i][0], s[i][0], s[i][1]);
            unpack2(s2[i][1], s[i][2], s[i][3]);
            #pragma unroll
            for (int j = 0; j < 4; j++) {
                float v = s[i][j] * scale;
                if (need_mask && (jt * 64 + tx * 4 + j > q0 + ty * 8 + i)) v = -1e30f;
                s[i][j] = v;
            }
        }

        #pragma unroll
        for (int i = 0; i < 8; i++) {
            float rm = fmaxf(fmaxf(s[i][0], s[i][1]), fmaxf(s[i][2], s[i][3]));
            rm = fmaxf(rm, __shfl_xor_sync(0xffffffffu, rm, 1, 16));
            rm = fmaxf(rm, __shfl_xor_sync(0xffffffffu, rm, 2, 16));
            rm = fmaxf(rm, __shfl_xor_sync(0xffffffffu, rm, 4, 16));
            rm = fmaxf(rm, __shfl_xor_sync(0xffffffffu, rm, 8, 16));
            float mn    = fmaxf(m[i], rm);
            float alpha = __expf(m[i] - mn);
            m[i] = mn;
            float rs = 0.f;
            #pragma unroll
            for (int j = 0; j < 4; j++) {
                float p = __expf(s[i][j] - mn);
                s[i][j] = p;
                rs += p;
            }
            rs += __shfl_xor_sync(0xffffffffu, rs, 1, 16);
            rs += __shfl_xor_sync(0xffffffffu, rs, 2, 16);
            rs += __shfl_xor_sync(0xffffffffu, rs, 4, 16);
            rs += __shfl_xor_sync(0xffffffffu, rs, 8, 16);
            l[i] = l[i] * alpha + rs;
            u64 al2 = pack2(alpha, alpha);
            accO[i][0] = mul2(accO[i][0], al2);
            accO[i][1] = mul2(accO[i][1], al2);
        }

        #pragma unroll
        for (int i = 0; i < 8; i++)
            #pragma unroll
            for (int j = 0; j < 4; j++)
                Ps[(tx * 4 + j) * PPAD + ty * 8 + i] = s[i][j];
        __syncthreads();

        #pragma unroll 8
        for (int k = 0; k < 64; k++) {
            float4 pp0 = *(const float4*)&Ps[k * PPAD + ty * 8];
            float4 pp1 = *(const float4*)&Ps[k * PPAD + ty * 8 + 4];
            float4 vv  = *(const float4*)&Vs[k * KPAD + tx * 4];
            u64 v20 = pack2(vv.x, vv.y);
            u64 v21 = pack2(vv.z, vv.w);
            float pv[8] = {pp0.x, pp0.y, pp0.z, pp0.w, pp1.x, pp1.y, pp1.z, pp1.w};
            #pragma unroll
            for (int i = 0; i < 8; i++) {
                u64 p2 = pack2(pv[i], pv[i]);
                fma2(accO[i][0], p2, v20);
                fma2(accO[i][1], p2, v21);
            }
        }
    }

    #pragma unroll
    for (int i = 0; i < 8; i++) {
        float inv = 1.f / l[i];
        float o0, o1, o2, o3;
        unpack2(accO[i][0], o0, o1);
        unpack2(accO[i][1], o2, o3);
        size_t r = (size_t)b * S_ + q0 + ty * 8 + i;
        *(float4*)&g_o[(r * NH_ + h) * DH_ + tx * 4] =
            make_float4(o0 * inv, o1 * inv, o2 * inv, o3 * inv);
    }
}

// ---------------------------------------------------------------------------
// launch
// ---------------------------------------------------------------------------
extern "C" void kernel_launch(void* const* d_in, const int* in_sizes, int n_in,
                              void* d_out, int out_size)
{
    const float* X   = (const float*)d_in[0];
    const int*   pos = (const int*)  d_in[1];
    const float* Wq  = (const float*)d_in[2];
    const float* Wk  = (const float*)d_in[3];
    const float* Wv  = (const float*)d_in[4];
    const float* Wo  = (const float*)d_in[5];
    float*       out = (float*)d_out;

    // device addresses of ALL symbols passed as kernel arguments
    void *pa2, *po, *pwq, *pwk, *pwv, *pwo;
    cudaGetSymbolAddress(&pa2, g_a2);
    cudaGetSymbolAddress(&po,  g_o);
    cudaGetSymbolAddress(&pwq, g_wq2);
    cudaGetSymbolAddress(&pwk, g_wk2);
    cudaGetSymbolAddress(&pwv, g_wv2);
    cudaGetSymbolAddress(&pwo, g_wo2);

    cudaFuncSetAttribute(flash_kernel, cudaFuncAttributeMaxDynamicSharedMemorySize, FLASH_SMEM);

    invfreq_init_kernel<<<1, 32>>>();

    // bf16 split conversions
    cvt_hihilo<<<8192, 256>>>(X, (__nv_bfloat16*)pa2);
    cvt_w_T<<<dim3(64, 64), dim3(32, 8)>>>(Wq, (__nv_bfloat16*)pwq, 2048);
    cvt_w_T<<<dim3(16, 64), dim3(32, 8)>>>(Wk, (__nv_bfloat16*)pwk, 512);
    cvt_w_T<<<dim3(16, 64), dim3(32, 8)>>>(Wv, (__nv_bfloat16*)pwv, 512);
    cvt_w_T<<<dim3(64, 64), dim3(32, 8)>>>(Wo, (__nv_bfloat16*)pwo, 2048);

    // QKV projections on tensor cores (mma.sync bf16x3)
    qkv_mma<<<768, 256>>>();

    // RoPE
    {
        const int TOT = M_ * (NH_ + NKV_) * (DH_ / 2);
        rope_kernel<<<(TOT + 255) / 256, 256>>>(pos);
    }

    // causal GQA attention
    flash_kernel<<<dim3(S_ / 128, NH_, B_), 256, FLASH_SMEM>>>();

    // output projection on tensor cores
    cvt_hihilo<<<8192, 256>>>((const float*)po, (__nv_bfloat16*)pa2);
    out_mma<<<512, 256>>>(out);
}

// round 8
// speedup vs baseline: 1.9502x; 1.2464x over previous
#include <cuda_runtime.h>
#include <cuda_bf16.h>
#include <math.h>
#include <cstdint>

#define B_   2
#define S_   2048
#define H_   2048
#define NH_  32
#define NKV_ 8
#define DH_  64
#define M_   (B_*S_)      // 4096 rows
#define KP_  6144         // 3*H_ : A'=[hi|hi|lo], W'=[hi|lo|hi]

typedef unsigned long long u64;

// ---------------------------------------------------------------------------
// Scratch (static device globals; no runtime allocation)
// ---------------------------------------------------------------------------
__device__ float g_q[(size_t)M_ * NH_ * DH_];     // fp32 QKV intermediates
__device__ float g_k[(size_t)M_ * NKV_ * DH_];
__device__ float g_v[(size_t)M_ * NKV_ * DH_];
__device__ float g_invfreq[DH_ / 2];

__device__ __align__(128) __nv_bfloat16 g_a2 [(size_t)M_   * KP_];  // X' then O'
__device__ __align__(128) __nv_bfloat16 g_wq2[(size_t)2048 * KP_];
__device__ __align__(128) __nv_bfloat16 g_wk2[(size_t)512  * KP_];
__device__ __align__(128) __nv_bfloat16 g_wv2[(size_t)512  * KP_];
__device__ __align__(128) __nv_bfloat16 g_wo2[(size_t)2048 * KP_];

// split attention operands
__device__ __align__(128) __nv_bfloat16 g_q2 [(size_t)B_ * NH_  * S_ * 128]; // [b][h][s][qh64|ql64], pre-scaled 1/8
__device__ __align__(128) __nv_bfloat16 g_k2 [(size_t)B_ * NKV_ * S_ * 128]; // [b][kvh][s][kh64|kl64]
__device__ __align__(128) __nv_bfloat16 g_v2t[(size_t)B_ * NKV_ * 64 * 2 * S_]; // [b][kvh][d][hi/lo][s]

// ---------------------------------------------------------------------------
// helpers
// ---------------------------------------------------------------------------
__device__ __forceinline__ void mma16816(float* d, const uint32_t* a, const uint32_t* b) {
    asm volatile("mma.sync.aligned.m16n8k16.row.col.f32.bf16.bf16.f32 "
                 "{%0,%1,%2,%3}, {%4,%5,%6,%7}, {%8,%9}, {%0,%1,%2,%3};"
                 : "+f"(d[0]), "+f"(d[1]), "+f"(d[2]), "+f"(d[3])
                 : "r"(a[0]), "r"(a[1]), "r"(a[2]), "r"(a[3]), "r"(b[0]), "r"(b[1]));
}
__device__ __forceinline__ uint32_t packbf(float a, float b) {
    __nv_bfloat162 p = __halves2bfloat162(__float2bfloat16_rn(a), __float2bfloat16_rn(b));
    return *(uint32_t*)&p;
}

// ---------------------------------------------------------------------------
// inv_freq init
// ---------------------------------------------------------------------------
__global__ void invfreq_init_kernel() {
    int i = threadIdx.x;
    if (i < DH_ / 2) {
        g_invfreq[i] = (float)(1.0 / pow(10000.0, (double)(2 * i) / (double)DH_));
    }
}

// ---------------------------------------------------------------------------
// hi/hi/lo split: src fp32 [4096, 2048] -> dst bf16 [4096, 6144]
// ---------------------------------------------------------------------------
__global__ __launch_bounds__(256) void cvt_hihilo(const float* __restrict__ src,
                                                  __nv_bfloat16* __restrict__ dst)
{
    int t = blockIdx.x * blockDim.x + threadIdx.x;
    int m  = t >> 9;
    int c4 = (t & 511) * 4;
    float4 x = *(const float4*)(src + (size_t)m * 2048 + c4);

    __nv_bfloat16 h0 = __float2bfloat16_rn(x.x), h1 = __float2bfloat16_rn(x.y);
    __nv_bfloat16 h2 = __float2bfloat16_rn(x.z), h3 = __float2bfloat16_rn(x.w);
    __nv_bfloat16 l0 = __float2bfloat16_rn(x.x - __bfloat162float(h0));
    __nv_bfloat16 l1 = __float2bfloat16_rn(x.y - __bfloat162float(h1));
    __nv_bfloat16 l2 = __float2bfloat16_rn(x.z - __bfloat162float(h2));
    __nv_bfloat16 l3 = __float2bfloat16_rn(x.w - __bfloat162float(h3));

    __nv_bfloat162 H01 = __halves2bfloat162(h0, h1), H23 = __halves2bfloat162(h2, h3);
    __nv_bfloat162 L01 = __halves2bfloat162(l0, l1), L23 = __halves2bfloat162(l2, l3);
    uint2 Hv = make_uint2(*(uint32_t*)&H01, *(uint32_t*)&H23);
    uint2 Lv = make_uint2(*(uint32_t*)&L01, *(uint32_t*)&L23);

    size_t base = (size_t)m * KP_ + c4;
    *(uint2*)(dst + base)        = Hv;
    *(uint2*)(dst + base + 2048) = Hv;
    *(uint2*)(dst + base + 4096) = Lv;
}

// ---------------------------------------------------------------------------
// Weight transpose + split: W fp32 [2048, Nout] -> W' bf16 [Nout, 6144]
// ---------------------------------------------------------------------------
__global__ __launch_bounds__(256) void cvt_w_T(const float* __restrict__ W,
                                               __nv_bfloat16* __restrict__ Wp, int Nout)
{
    __shared__ float tile[32][33];
    int tx = threadIdx.x, ty = threadIdx.y;
    int n0 = blockIdx.x * 32, k0 = blockIdx.y * 32;

    #pragma unroll
    for (int r = 0; r < 4; r++)
        tile[ty + r * 8][tx] = W[(size_t)(k0 + ty + r * 8) * Nout + n0 + tx];
    __syncthreads();

    #pragma unroll
    for (int r = 0; r < 4; r++) {
        int nl = ty + r * 8, kl = tx;
        float v = tile[kl][nl];
        __nv_bfloat16 h = __float2bfloat16_rn(v);
        __nv_bfloat16 l = __float2bfloat16_rn(v - __bfloat162float(h));
        size_t rowb = (size_t)(n0 + nl) * KP_;
        Wp[rowb + k0 + kl]        = h;
        Wp[rowb + 2048 + k0 + kl] = l;
        Wp[rowb + 4096 + k0 + kl] = h;
    }
}

// ---------------------------------------------------------------------------
// bf16 mma.sync GEMM (proven in R7). 128x128 CTA tile, 8 warps (2x4).
// ---------------------------------------------------------------------------
#define KSLAB 32
#define NSLAB (KP_ / KSLAB)     // 192
#define ARS   40

__device__ __forceinline__ void mma_gemm_body(
    const __nv_bfloat16* __restrict__ A2, const __nv_bfloat16* __restrict__ W2,
    float* __restrict__ C, int Nout, int row0, int col0)
{
    __shared__ __nv_bfloat16 As[128][ARS];
    __shared__ __nv_bfloat16 Bs[128][ARS];

    const int tid  = threadIdx.x;
    const int lane = tid & 31;
    const int wid  = tid >> 5;
    const int wm   = wid >> 2;
    const int wn   = wid & 3;
    const int g    = lane >> 2;
    const int tq   = lane & 3;

    const int lrow = tid >> 2;
    const int lk   = (tid & 3) * 8;

    const __nv_bfloat16* Ag = A2 + (size_t)(row0 + lrow) * KP_ + lk;
    const __nv_bfloat16* Bg = W2 + (size_t)(col0 + lrow) * KP_ + lk;

    float acc[4][4][4];
    #pragma unroll
    for (int i = 0; i < 4; i++)
        #pragma unroll
        for (int j = 0; j < 4; j++)
            #pragma unroll
            for (int c = 0; c < 4; c++) acc[i][j][c] = 0.f;

    for (int s = 0; s < NSLAB; s++) {
        uint4 a0 = *(const uint4*)(Ag + s * KSLAB);
        uint4 a1 = *(const uint4*)(Ag + s * KSLAB + (size_t)64 * KP_);
        uint4 b0 = *(const uint4*)(Bg + s * KSLAB);
        uint4 b1 = *(const uint4*)(Bg + s * KSLAB + (size_t)64 * KP_);

        __syncthreads();
        *(uint4*)&As[lrow][lk]      = a0;
        *(uint4*)&As[lrow + 64][lk] = a1;
        *(uint4*)&Bs[lrow][lk]      = b0;
        *(uint4*)&Bs[lrow + 64][lk] = b1;
        __syncthreads();

        #pragma unroll
        for (int ks = 0; ks < 2; ks++) {
            const int c0 = tq * 2 + ks * 16;
            uint32_t af[4][4];
            #pragma unroll
            for (int mt = 0; mt < 4; mt++) {
                const int r = wm * 64 + mt * 16 + g;
                af[mt][0] = *(const uint32_t*)&As[r][c0];
                af[mt][1] = *(const uint32_t*)&As[r + 8][c0];
                af[mt][2] = *(const uint32_t*)&As[r][c0 + 8];
                af[mt][3] = *(const uint32_t*)&As[r + 8][c0 + 8];
            }
            uint32_t bf[4][2];
            #pragma unroll
            for (int nt = 0; nt < 4; nt++) {
                const int n = wn * 32 + nt * 8 + g;
                bf[nt][0] = *(const uint32_t*)&Bs[n][c0];
                bf[nt][1] = *(const uint32_t*)&Bs[n][c0 + 8];
            }
            #pragma unroll
            for (int mt = 0; mt < 4; mt++)
                #pragma unroll
                for (int nt = 0; nt < 4; nt++)
                    mma16816(acc[mt][nt], af[mt], bf[nt]);
        }
    }

    #pragma unroll
    for (int mt = 0; mt < 4; mt++) {
        #pragma unroll
        for (int nt = 0; nt < 4; nt++) {
            int row = row0 + wm * 64 + mt * 16 + g;
            int col = col0 + wn * 32 + nt * 8 + tq * 2;
            *(float2*)&C[(size_t)row * Nout + col] =
                make_float2(acc[mt][nt][0], acc[mt][nt][1]);
            *(float2*)&C[(size_t)(row + 8) * Nout + col] =
                make_float2(acc[mt][nt][2], acc[mt][nt][3]);
        }
    }
}

__global__ __launch_bounds__(256, 2) void qkv_mma()
{
    const int bx = blockIdx.x;
    if (bx < 512)
        mma_gemm_body(g_a2, g_wq2, g_q, NH_ * DH_, (bx >> 4) * 128, (bx & 15) * 128);
    else if (bx < 640) {
        int t = bx - 512;
        mma_gemm_body(g_a2, g_wk2, g_k, NKV_ * DH_, (t >> 2) * 128, (t & 3) * 128);
    } else {
        int t = bx - 640;
        mma_gemm_body(g_a2, g_wv2, g_v, NKV_ * DH_, (t >> 2) * 128, (t & 3) * 128);
    }
}

__global__ __launch_bounds__(256, 2) void out_mma(float* __restrict__ out)
{
    const int bx = blockIdx.x;
    mma_gemm_body(g_a2, g_wo2, out, H_, (bx >> 4) * 128, (bx & 15) * 128);
}

// ---------------------------------------------------------------------------
// RoPE + hi/lo split: reads g_q/g_k fp32, writes g_q2 (scaled 1/8) and g_k2.
// ---------------------------------------------------------------------------
__global__ __launch_bounds__(256) void rope_split_kernel(const int* __restrict__ pos_ids)
{
    const int TOT = M_ * (NH_ + NKV_) * 32;
    int t = blockIdx.x * blockDim.x + threadIdx.x;
    if (t >= TOT) return;

    int i  = t & 31;
    int h  = (t >> 5) % (NH_ + NKV_);
    int bs = t / (32 * (NH_ + NKV_));
    int b  = bs >> 11, s = bs & 2047;

    float pos = (float)pos_ids[bs];
    float f = pos * g_invfreq[i];
    float sn, c;
    sincosf(f, &sn, &c);

    const float* base;
    __nv_bfloat16* dst;
    float scale;
    if (h < NH_) {
        base  = g_q + (size_t)bs * (NH_ * DH_) + h * DH_;
        dst   = g_q2 + ((size_t)(b * NH_ + h) * S_ + s) * 128;
        scale = 0.125f;
    } else {
        base  = g_k + (size_t)bs * (NKV_ * DH_) + (h - NH_) * DH_;
        dst   = g_k2 + ((size_t)(b * NKV_ + (h - NH_)) * S_ + s) * 128;
        scale = 1.0f;
    }

    float x1 = base[i], x2 = base[i + 32];
    float o1 = (x1 * c - x2 * sn) * scale;
    float o2 = (x2 * c + x1 * sn) * scale;

    __nv_bfloat16 h1 = __float2bfloat16_rn(o1);
    __nv_bfloat16 h2 = __float2bfloat16_rn(o2);
    dst[i]           = h1;
    dst[i + 32]      = h2;
    dst[64 + i]      = __float2bfloat16_rn(o1 - __bfloat162float(h1));
    dst[64 + i + 32] = __float2bfloat16_rn(o2 - __bfloat162float(h2));
}

// ---------------------------------------------------------------------------
// V transpose + split: g_v fp32 [m][512] -> g_v2t [b][kvh][d][hi/lo][s]
// ---------------------------------------------------------------------------
__global__ __launch_bounds__(256) void cvt_v_kernel()
{
    __shared__ float tile[32][33];
    int tx = threadIdx.x, ty = threadIdx.y;
    int s0 = blockIdx.x * 32;
    int cb = blockIdx.y;            // 0..15 : 32-col block of the 512 V cols
    int b  = blockIdx.z;
    int kvh = cb >> 1, dbase = (cb & 1) * 32;

    #pragma unroll
    for (int r = 0; r < 4; r++)
        tile[ty + r * 8][tx] = g_v[(size_t)(b * S_ + s0 + ty + r * 8) * 512 + cb * 32 + tx];
    __syncthreads();

    #pragma unroll
    for (int r = 0; r < 4; r++) {
        int dl = ty + r * 8;
        float v = tile[tx][dl];
        __nv_bfloat16 h = __float2bfloat16_rn(v);
        __nv_bfloat16 l = __float2bfloat16_rn(v - __bfloat162float(h));
        size_t obase = (((size_t)(b * NKV_ + kvh) * 64 + dbase + dl) * 2) * S_;
        g_v2t[obase + s0 + tx]      = h;
        g_v2t[obase + S_ + s0 + tx] = l;
    }
}

// ---------------------------------------------------------------------------
// Flash attention on HMMA. CTA: 128 q-rows x 64-kv tiles; 8 warps x 16 rows.
// 3-term bf16 split on both QK^T (d-ext) and PV (c-ext).
// Writes O directly in [hi|hi|lo] layout into g_a2.
// ---------------------------------------------------------------------------
#define FSP   136                       // smem row stride (bf16) for 128-wide rows
#define F_KS  0
#define F_VT  (64 * FSP)
#define F_PS  (128 * FSP)
#define FLASH_SMEM ((F_PS + 128 * FSP) * 2)   // 69632 bytes

__global__ __launch_bounds__(256) void flash_mma()
{
    extern __shared__ __nv_bfloat16 smx[];
    __nv_bfloat16* Ks = smx + F_KS;     // [64 c][kh64|kl64]
    __nv_bfloat16* Vt = smx + F_VT;     // [64 d][vh(c)64|vl(c)64]
    __nv_bfloat16* Ps = smx + F_PS;     // [128 r][ph64|pl64]

    const int tid  = threadIdx.x;
    const int lane = tid & 31;
    const int wq   = tid >> 5;          // warp -> 16-row block
    const int g    = lane >> 2;
    const int tq   = lane & 3;

    const int jq  = (gridDim.x - 1) - blockIdx.x;   // heavy first
    const int h   = blockIdx.y;
    const int b   = blockIdx.z;
    const int kvh = h >> 2;
    const int q0  = jq * 128;

    const __nv_bfloat16* qbase = g_q2 + ((size_t)(b * NH_ + h) * S_ + q0 + wq * 16) * 128;
    const __nv_bfloat16* kbase = g_k2 + (size_t)(b * NKV_ + kvh) * S_ * 128;
    const __nv_bfloat16* vbase = g_v2t + (size_t)(b * NKV_ + kvh) * 64 * 2 * S_;

    float m0 = -1e30f, m1 = -1e30f, l0 = 0.f, l1 = 0.f;
    float accO[8][4];
    #pragma unroll
    for (int nt = 0; nt < 8; nt++)
        #pragma unroll
        for (int c = 0; c < 4; c++) accO[nt][c] = 0.f;

    const int ntiles = 2 * jq + 2;
    for (int jt = 0; jt < ntiles; jt++) {
        __syncthreads();   // prev PV done / smem free
        // ---- stage K and Vt tiles ----
        {
            int c  = tid >> 2, seg = tid & 3;
            const uint4* ksrc = (const uint4*)(kbase + (size_t)(jt * 64 + c) * 128 + seg * 32);
            uint4* kdst = (uint4*)(Ks + c * FSP + seg * 32);
            kdst[0] = ksrc[0]; kdst[1] = ksrc[1]; kdst[2] = ksrc[2]; kdst[3] = ksrc[3];

            int d = tid >> 2, part = (tid & 3) >> 1, so = (tid & 1) * 32;
            const uint4* vsrc = (const uint4*)(vbase + ((size_t)d * 2 + part) * S_ + jt * 64 + so);
            uint4* vdst = (uint4*)(Vt + d * FSP + part * 64 + so);
            vdst[0] = vsrc[0]; vdst[1] = vsrc[1]; vdst[2] = vsrc[2]; vdst[3] = vsrc[3];
        }
        __syncthreads();

        // ---- Q fragments (from global, L1-resident) ----
        uint32_t qf[8][4];
        #pragma unroll
        for (int pc = 0; pc < 8; pc++) {
            int c = pc * 16 + tq * 2;
            qf[pc][0] = *(const uint32_t*)(qbase + (size_t)g * 128 + c);
            qf[pc][1] = *(const uint32_t*)(qbase + (size_t)(g + 8) * 128 + c);
            qf[pc][2] = *(const uint32_t*)(qbase + (size_t)g * 128 + c + 8);
            qf[pc][3] = *(const uint32_t*)(qbase + (size_t)(g + 8) * 128 + c + 8);
        }

        // ---- S = (Q/8) K^T : qh*kh + ql*kh + qh*kl ----
        float sa[8][4];
        #pragma unroll
        for (int nt = 0; nt < 8; nt++)
            #pragma unroll
            for (int c = 0; c < 4; c++) sa[nt][c] = 0.f;

        #pragma unroll
        for (int kc = 0; kc < 4; kc++) {
            #pragma unroll
            for (int nt = 0; nt < 8; nt++) {
                int n = nt * 8 + g;
                uint32_t bb[2];
                bb[0] = *(const uint32_t*)(Ks + n * FSP + kc * 16 + tq * 2);
                bb[1] = *(const uint32_t*)(Ks + n * FSP + kc * 16 + tq * 2 + 8);
                mma16816(sa[nt], qf[kc],     bb);   // qh*kh
                mma16816(sa[nt], qf[kc + 4], bb);   // ql*kh
            }
        }
        #pragma unroll
        for (int kc = 4; kc < 8; kc++) {
            #pragma unroll
            for (int nt = 0; nt < 8; nt++) {
                int n = nt * 8 + g;
                uint32_t bb[2];
                bb[0] = *(const uint32_t*)(Ks + n * FSP + kc * 16 + tq * 2);
                bb[1] = *(const uint32_t*)(Ks + n * FSP + kc * 16 + tq * 2 + 8);
                mma16816(sa[nt], qf[kc - 4], bb);   // qh*kl
            }
        }

        // ---- causal mask ----
        const float NEG = -1e30f;
        if (jt >= 2 * jq) {
            int rg0 = q0 + wq * 16 + g, rg1 = rg0 + 8;
            #pragma unroll
            for (int nt = 0; nt < 8; nt++) {
                int cg = jt * 64 + nt * 8 + tq * 2;
                if (cg     > rg0) sa[nt][0] = NEG;
                if (cg + 1 > rg0) sa[nt][1] = NEG;
                if (cg     > rg1) sa[nt][2] = NEG;
                if (cg + 1 > rg1) sa[nt][3] = NEG;
            }
        }

        // ---- online softmax ----
        float rm0 = NEG, rm1 = NEG;
        #pragma unroll
        for (int nt = 0; nt < 8; nt++) {
            rm0 = fmaxf(rm0, fmaxf(sa[nt][0], sa[nt][1]));
            rm1 = fmaxf(rm1, fmaxf(sa[nt][2], sa[nt][3]));
        }
        rm0 = fmaxf(rm0, __shfl_xor_sync(0xffffffffu, rm0, 1));
        rm0 = fmaxf(rm0, __shfl_xor_sync(0xffffffffu, rm0, 2));
        rm1 = fmaxf(rm1, __shfl_xor_sync(0xffffffffu, rm1, 1));
        rm1 = fmaxf(rm1, __shfl_xor_sync(0xffffffffu, rm1, 2));

        float mn0 = fmaxf(m0, rm0), mn1 = fmaxf(m1, rm1);
        float al0 = __expf(m0 - mn0), al1 = __expf(m1 - mn1);
        m0 = mn0; m1 = mn1;

        float rs0 = 0.f, rs1 = 0.f;
        float p[8][4];
        #pragma unroll
        for (int nt = 0; nt < 8; nt++) {
            p[nt][0] = __expf(sa[nt][0] - mn0);
            p[nt][1] = __expf(sa[nt][1] - mn0);
            p[nt][2] = __expf(sa[nt][2] - mn1);
            p[nt][3] = __expf(sa[nt][3] - mn1);
            rs0 += p[nt][0] + p[nt][1];
            rs1 += p[nt][2] + p[nt][3];
        }
        rs0 += __shfl_xor_sync(0xffffffffu, rs0, 1);
        rs0 += __shfl_xor_sync(0xffffffffu, rs0, 2);
        rs1 += __shfl_xor_sync(0xffffffffu, rs1, 1);
        rs1 += __shfl_xor_sync(0xffffffffu, rs1, 2);
        l0 = l0 * al0 + rs0;
        l1 = l1 * al1 + rs1;

        #pragma unroll
        for (int nt = 0; nt < 8; nt++) {
            accO[nt][0] *= al0; accO[nt][1] *= al0;
            accO[nt][2] *= al1; accO[nt][3] *= al1;
        }

        // ---- P -> smem (hi|lo) ----
        {
            int pr0 = wq * 16 + g, pr1 = pr0 + 8;
            #pragma unroll
            for (int nt = 0; nt < 8; nt++) {
                int col = nt * 8 + tq * 2;
                float p0 = p[nt][0], p1 = p[nt][1], p2 = p[nt][2], p3 = p[nt][3];
                __nv_bfloat16 h00 = __float2bfloat16_rn(p0), h01 = __float2bfloat16_rn(p1);
                __nv_bfloat16 h10 = __float2bfloat16_rn(p2), h11 = __float2bfloat16_rn(p3);
                *(uint32_t*)(Ps + pr0 * FSP + col) =
                    *(uint32_t*)&(__nv_bfloat162&)*(__nv_bfloat162[]){__halves2bfloat162(h00, h01)};
                *(uint32_t*)(Ps + pr1 * FSP + col) =
                    *(uint32_t*)&(__nv_bfloat162&)*(__nv_bfloat162[]){__halves2bfloat162(h10, h11)};
                *(uint32_t*)(Ps + pr0 * FSP + 64 + col) =
                    packbf(p0 - __bfloat162float(h00), p1 - __bfloat162float(h01));
                *(uint32_t*)(Ps + pr1 * FSP + 64 + col) =
                    packbf(p2 - __bfloat162float(h10), p3 - __bfloat162float(h11));
            }
        }
        __syncthreads();

        // ---- O += P V : ph*vh + pl*vh + ph*vl ----
        uint32_t ap[8][4];
        {
            int pr = wq * 16 + g;
            #pragma unroll
            for (int pc = 0; pc < 8; pc++) {
                int c = pc * 16 + tq * 2;
                ap[pc][0] = *(const uint32_t*)(Ps + pr * FSP + c);
                ap[pc][1] = *(const uint32_t*)(Ps + (pr + 8) * FSP + c);
                ap[pc][2] = *(const uint32_t*)(Ps + pr * FSP + c + 8);
                ap[pc][3] = *(const uint32_t*)(Ps + (pr + 8) * FSP + c + 8);
            }
        }
        #pragma unroll
        for (int vc = 0; vc < 4; vc++) {
            #pragma unroll
            for (int nt = 0; nt < 8; nt++) {
                int n = nt * 8 + g;
                uint32_t bb[2];
                bb[0] = *(const uint32_t*)(Vt + n * FSP + vc * 16 + tq * 2);
                bb[1] = *(const uint32_t*)(Vt + n * FSP + vc * 16 + tq * 2 + 8);
                mma16816(accO[nt], ap[vc],     bb);
                mma16816(accO[nt], ap[vc + 4], bb);
            }
        }
        #pragma unroll
        for (int vc = 4; vc < 8; vc++) {
            #pragma unroll
            for (int nt = 0; nt < 8; nt++) {
                int n = nt * 8 + g;
                uint32_t bb[2];
                bb[0] = *(const uint32_t*)(Vt + n * FSP + vc * 16 + tq * 2);
                bb[1] = *(const uint32_t*)(Vt + n * FSP + vc * 16 + tq * 2 + 8);
                mma16816(accO[nt], ap[vc - 4], bb);
            }
        }
    }

    // ---- epilogue: write O' = [hi|hi|lo] into g_a2 ----
    float inv0 = 1.f / l0, inv1 = 1.f / l1;
    size_t r0 = (size_t)b * S_ + q0 + wq * 16 + g;
    #pragma unroll
    for (int nt = 0; nt < 8; nt++) {
        int c = h * 64 + nt * 8 + tq * 2;
        float o00 = accO[nt][0] * inv0, o01 = accO[nt][1] * inv0;
        float o10 = accO[nt][2] * inv1, o11 = accO[nt][3] * inv1;

        __nv_bfloat16 h00 = __float2bfloat16_rn(o00), h01 = __float2bfloat16_rn(o01);
        __nv_bfloat16 h10 = __float2bfloat16_rn(o10), h11 = __float2bfloat16_rn(o11);
        uint32_t hh0 = packbf(o00, o01);   // same as packing h00,h01
        uint32_t hh1 = packbf(o10, o11);
        uint32_t ll0 = packbf(o00 - __bfloat162float(h00), o01 - __bfloat162float(h01));
        uint32_t ll1 = packbf(o10 - __bfloat162float(h10), o11 - __bfloat162float(h11));

        __nv_bfloat16* d0 = g_a2 + r0 * KP_ + c;
        __nv_bfloat16* d1 = g_a2 + (r0 + 8) * KP_ + c;
        *(uint32_t*)(d0)        = hh0;
        *(uint32_t*)(d0 + 2048) = hh0;
        *(uint32_t*)(d0 + 4096) = ll0;
        *(uint32_t*)(d1)        = hh1;
        *(uint32_t*)(d1 + 2048) = hh1;
        *(uint32_t*)(d1 + 4096) = ll1;
    }
}

// ---------------------------------------------------------------------------
// launch
// ---------------------------------------------------------------------------
extern "C" void kernel_launch(void* const* d_in, const int* in_sizes, int n_in,
                              void* d_out, int out_size)
{
    const float* X   = (const float*)d_in[0];
    const int*   pos = (const int*)  d_in[1];
    const float* Wq  = (const float*)d_in[2];
    const float* Wk  = (const float*)d_in[3];
    const float* Wv  = (const float*)d_in[4];
    const float* Wo  = (const float*)d_in[5];
    float*       out = (float*)d_out;

    void *pa2, *pwq, *pwk, *pwv, *pwo;
    cudaGetSymbolAddress(&pa2, g_a2);
    cudaGetSymbolAddress(&pwq, g_wq2);
    cudaGetSymbolAddress(&pwk, g_wk2);
    cudaGetSymbolAddress(&pwv, g_wv2);
    cudaGetSymbolAddress(&pwo, g_wo2);

    cudaFuncSetAttribute(flash_mma, cudaFuncAttributeMaxDynamicSharedMemorySize, FLASH_SMEM);

    invfreq_init_kernel<<<1, 32>>>();

    cvt_hihilo<<<8192, 256>>>(X, (__nv_bfloat16*)pa2);
    cvt_w_T<<<dim3(64, 64), dim3(32, 8)>>>(Wq, (__nv_bfloat16*)pwq, 2048);
    cvt_w_T<<<dim3(16, 64), dim3(32, 8)>>>(Wk, (__nv_bfloat16*)pwk, 512);
    cvt_w_T<<<dim3(16, 64), dim3(32, 8)>>>(Wv, (__nv_bfloat16*)pwv, 512);
    cvt_w_T<<<dim3(64, 64), dim3(32, 8)>>>(Wo, (__nv_bfloat16*)pwo, 2048);

    qkv_mma<<<768, 256>>>();

    {
        const int TOT = M_ * (NH_ + NKV_) * 32;
        rope_split_kernel<<<(TOT + 255) / 256, 256>>>(pos);
    }
    cvt_v_kernel<<<dim3(64, 16, 2), dim3(32, 8)>>>();

    flash_mma<<<dim3(S_ / 128, NH_, B_), 256, FLASH_SMEM>>>();

    out_mma<<<512, 256>>>(out);
}

// round 9
// speedup vs baseline: 2.7871x; 1.4291x over previous
#include <cuda_runtime.h>
#include <cuda_fp16.h>
#include <math.h>
#include <cstdint>

#define B_   2
#define S_   2048
#define H_   2048
#define NH_  32
#define NKV_ 8
#define DH_  64
#define M_   (B_*S_)      // 4096 rows
#define KA_  4096         // A' k-ext: [hi | lo]
#define KW_  2048         // W stored once (hi); k-index wraps

typedef unsigned long long u64;

// ---------------------------------------------------------------------------
// Scratch (static device globals; no runtime allocation)
// ---------------------------------------------------------------------------
__device__ float g_q[(size_t)M_ * NH_ * DH_];     // fp32 QKV intermediates
__device__ float g_k[(size_t)M_ * NKV_ * DH_];
__device__ float g_v[(size_t)M_ * NKV_ * DH_];
__device__ float g_invfreq[DH_ / 2];

__device__ __align__(128) __half g_a2 [(size_t)M_   * KA_];  // X'=[hi|lo], then O'
__device__ __align__(128) __half g_wq2[(size_t)2048 * KW_];  // [N,2048] hi only
__device__ __align__(128) __half g_wk2[(size_t)512  * KW_];
__device__ __align__(128) __half g_wv2[(size_t)512  * KW_];
__device__ __align__(128) __half g_wo2[(size_t)2048 * KW_];

// split attention operands
__device__ __align__(128) __half g_q2 [(size_t)B_ * NH_  * S_ * 128]; // [qh64|ql64], pre-scaled 1/8
__device__ __align__(128) __half g_k2 [(size_t)B_ * NKV_ * S_ * 64];  // kh only
__device__ __align__(128) __half g_v2t[(size_t)B_ * NKV_ * 64 * S_];  // [d][s] vh only

// ---------------------------------------------------------------------------
// helpers
// ---------------------------------------------------------------------------
__device__ __forceinline__ void mma16816(float* d, const uint32_t* a, const uint32_t* b) {
    asm volatile("mma.sync.aligned.m16n8k16.row.col.f32.f16.f16.f32 "
                 "{%0,%1,%2,%3}, {%4,%5,%6,%7}, {%8,%9}, {%0,%1,%2,%3};"
                 : "+f"(d[0]), "+f"(d[1]), "+f"(d[2]), "+f"(d[3])
                 : "r"(a[0]), "r"(a[1]), "r"(a[2]), "r"(a[3]), "r"(b[0]), "r"(b[1]));
}
__device__ __forceinline__ uint32_t packh(float a, float b) {
    __half2 p = __halves2half2(__float2half_rn(a), __float2half_rn(b));
    return *(uint32_t*)&p;
}

// ---------------------------------------------------------------------------
// inv_freq init
// ---------------------------------------------------------------------------
__global__ void invfreq_init_kernel() {
    int i = threadIdx.x;
    if (i < DH_ / 2) {
        g_invfreq[i] = (float)(1.0 / pow(10000.0, (double)(2 * i) / (double)DH_));
    }
}

// ---------------------------------------------------------------------------
// hi/lo split: src fp32 [4096, 2048] -> dst f16 [4096, 4096] = [hi|lo]
// ---------------------------------------------------------------------------
__global__ __launch_bounds__(256) void cvt_hilo(const float* __restrict__ src,
                                                __half* __restrict__ dst)
{
    int t = blockIdx.x * blockDim.x + threadIdx.x;
    int m  = t >> 9;
    int c4 = (t & 511) * 4;
    float4 x = *(const float4*)(src + (size_t)m * 2048 + c4);

    __half h0 = __float2half_rn(x.x), h1 = __float2half_rn(x.y);
    __half h2 = __float2half_rn(x.z), h3 = __float2half_rn(x.w);
    __half l0 = __float2half_rn(x.x - __half2float(h0));
    __half l1 = __float2half_rn(x.y - __half2float(h1));
    __half l2 = __float2half_rn(x.z - __half2float(h2));
    __half l3 = __float2half_rn(x.w - __half2float(h3));

    __half2 H01 = __halves2half2(h0, h1), H23 = __halves2half2(h2, h3);
    __half2 L01 = __halves2half2(l0, l1), L23 = __halves2half2(l2, l3);
    uint2 Hv = make_uint2(*(uint32_t*)&H01, *(uint32_t*)&H23);
    uint2 Lv = make_uint2(*(uint32_t*)&L01, *(uint32_t*)&L23);

    size_t base = (size_t)m * KA_ + c4;
    *(uint2*)(dst + base)        = Hv;
    *(uint2*)(dst + base + 2048) = Lv;
}

// ---------------------------------------------------------------------------
// Weight transpose: W fp32 [2048, Nout] -> W' f16 [Nout, 2048] (hi only)
// ---------------------------------------------------------------------------
__global__ __launch_bounds__(256) void cvt_w_T(const float* __restrict__ W,
                                               __half* __restrict__ Wp, int Nout)
{
    __shared__ float tile[32][33];
    int tx = threadIdx.x, ty = threadIdx.y;
    int n0 = blockIdx.x * 32, k0 = blockIdx.y * 32;

    #pragma unroll
    for (int r = 0; r < 4; r++)
        tile[ty + r * 8][tx] = W[(size_t)(k0 + ty + r * 8) * Nout + n0 + tx];
    __syncthreads();

    #pragma unroll
    for (int r = 0; r < 4; r++) {
        int nl = ty + r * 8, kl = tx;
        Wp[(size_t)(n0 + nl) * KW_ + k0 + kl] = __float2half_rn(tile[kl][nl]);
    }
}

// ---------------------------------------------------------------------------
// f16 mma.sync GEMM: C = A'[M,4096] @ W'[N,2048,wrapped]^T
// 128x128 CTA tile, 8 warps (2x4), K-slab 32, proven pipeline.
// ---------------------------------------------------------------------------
#define KSLAB 32
#define NSLAB (KA_ / KSLAB)     // 128
#define ARS   40

__device__ __forceinline__ void mma_gemm_body(
    const __half* __restrict__ A2, const __half* __restrict__ W2,
    float* __restrict__ C, int Nout, int row0, int col0)
{
    __shared__ __half As[128][ARS];
    __shared__ __half Bs[128][ARS];

    const int tid  = threadIdx.x;
    const int lane = tid & 31;
    const int wid  = tid >> 5;
    const int wm   = wid >> 2;
    const int wn   = wid & 3;
    const int g    = lane >> 2;
    const int tq   = lane & 3;

    const int lrow = tid >> 2;
    const int lk   = (tid & 3) * 8;

    const __half* Ag = A2 + (size_t)(row0 + lrow) * KA_ + lk;
    const __half* Bg = W2 + (size_t)(col0 + lrow) * KW_ + lk;

    float acc[4][4][4];
    #pragma unroll
    for (int i = 0; i < 4; i++)
        #pragma unroll
        for (int j = 0; j < 4; j++)
            #pragma unroll
            for (int c = 0; c < 4; c++) acc[i][j][c] = 0.f;

    for (int s = 0; s < NSLAB; s++) {
        const int ka = s * KSLAB;
        const int kw = ka & (KW_ - 1);      // W wraps: seg1 = seg0
        uint4 a0 = *(const uint4*)(Ag + ka);
        uint4 a1 = *(const uint4*)(Ag + ka + (size_t)64 * KA_);
        uint4 b0 = *(const uint4*)(Bg + kw);
        uint4 b1 = *(const uint4*)(Bg + kw + (size_t)64 * KW_);

        __syncthreads();
        *(uint4*)&As[lrow][lk]      = a0;
        *(uint4*)&As[lrow + 64][lk] = a1;
        *(uint4*)&Bs[lrow][lk]      = b0;
        *(uint4*)&Bs[lrow + 64][lk] = b1;
        __syncthreads();

        #pragma unroll
        for (int ks = 0; ks < 2; ks++) {
            const int c0 = tq * 2 + ks * 16;
            uint32_t af[4][4];
            #pragma unroll
            for (int mt = 0; mt < 4; mt++) {
                const int r = wm * 64 + mt * 16 + g;
                af[mt][0] = *(const uint32_t*)&As[r][c0];
                af[mt][1] = *(const uint32_t*)&As[r + 8][c0];
                af[mt][2] = *(const uint32_t*)&As[r][c0 + 8];
                af[mt][3] = *(const uint32_t*)&As[r + 8][c0 + 8];
            }
            uint32_t bf[4][2];
            #pragma unroll
            for (int nt = 0; nt < 4; nt++) {
                const int n = wn * 32 + nt * 8 + g;
                bf[nt][0] = *(const uint32_t*)&Bs[n][c0];
                bf[nt][1] = *(const uint32_t*)&Bs[n][c0 + 8];
            }
            #pragma unroll
            for (int mt = 0; mt < 4; mt++)
                #pragma unroll
                for (int nt = 0; nt < 4; nt++)
                    mma16816(acc[mt][nt], af[mt], bf[nt]);
        }
    }

    #pragma unroll
    for (int mt = 0; mt < 4; mt++) {
        #pragma unroll
        for (int nt = 0; nt < 4; nt++) {
            int row = row0 + wm * 64 + mt * 16 + g;
            int col = col0 + wn * 32 + nt * 8 + tq * 2;
            *(float2*)&C[(size_t)row * Nout + col] =
                make_float2(acc[mt][nt][0], acc[mt][nt][1]);
            *(float2*)&C[(size_t)(row + 8) * Nout + col] =
                make_float2(acc[mt][nt][2], acc[mt][nt][3]);
        }
    }
}

__global__ __launch_bounds__(256, 2) void qkv_mma()
{
    const int bx = blockIdx.x;
    if (bx < 512)
        mma_gemm_body(g_a2, g_wq2, g_q, NH_ * DH_, (bx >> 4) * 128, (bx & 15) * 128);
    else if (bx < 640) {
        int t = bx - 512;
        mma_gemm_body(g_a2, g_wk2, g_k, NKV_ * DH_, (t >> 2) * 128, (t & 3) * 128);
    } else {
        int t = bx - 640;
        mma_gemm_body(g_a2, g_wv2, g_v, NKV_ * DH_, (t >> 2) * 128, (t & 3) * 128);
    }
}

__global__ __launch_bounds__(256, 2) void out_mma(float* __restrict__ out)
{
    const int bx = blockIdx.x;
    mma_gemm_body(g_a2, g_wo2, out, H_, (bx >> 4) * 128, (bx & 15) * 128);
}

// ---------------------------------------------------------------------------
// RoPE + split: g_q -> g_q2 [qh|ql] scaled 1/8 ; g_k -> g_k2 [kh] only
// ---------------------------------------------------------------------------
__global__ __launch_bounds__(256) void rope_split_kernel(const int* __restrict__ pos_ids)
{
    const int TOT = M_ * (NH_ + NKV_) * 32;
    int t = blockIdx.x * blockDim.x + threadIdx.x;
    if (t >= TOT) return;

    int i  = t & 31;
    int h  = (t >> 5) % (NH_ + NKV_);
    int bs = t / (32 * (NH_ + NKV_));
    int b  = bs >> 11, s = bs & 2047;

    float pos = (float)pos_ids[bs];
    float f = pos * g_invfreq[i];
    float sn, c;
    sincosf(f, &sn, &c);

    if (h < NH_) {
        const float* base = g_q + (size_t)bs * (NH_ * DH_) + h * DH_;
        __half* dst = g_q2 + ((size_t)(b * NH_ + h) * S_ + s) * 128;
        float x1 = base[i], x2 = base[i + 32];
        float o1 = (x1 * c - x2 * sn) * 0.125f;
        float o2 = (x2 * c + x1 * sn) * 0.125f;
        __half h1 = __float2half_rn(o1);
        __half h2 = __float2half_rn(o2);
        dst[i]           = h1;
        dst[i + 32]      = h2;
        dst[64 + i]      = __float2half_rn(o1 - __half2float(h1));
        dst[64 + i + 32] = __float2half_rn(o2 - __half2float(h2));
    } else {
        const float* base = g_k + (size_t)bs * (NKV_ * DH_) + (h - NH_) * DH_;
        __half* dst = g_k2 + ((size_t)(b * NKV_ + (h - NH_)) * S_ + s) * 64;
        float x1 = base[i], x2 = base[i + 32];
        dst[i]      = __float2half_rn(x1 * c - x2 * sn);
        dst[i + 32] = __float2half_rn(x2 * c + x1 * sn);
    }
}

// ---------------------------------------------------------------------------
// V transpose: g_v fp32 [m][512] -> g_v2t f16 [b][kvh][d][s] (hi only)
// ---------------------------------------------------------------------------
__global__ __launch_bounds__(256) void cvt_v_kernel()
{
    __shared__ float tile[32][33];
    int tx = threadIdx.x, ty = threadIdx.y;
    int s0 = blockIdx.x * 32;
    int cb = blockIdx.y;
    int b  = blockIdx.z;
    int kvh = cb >> 1, dbase = (cb & 1) * 32;

    #pragma unroll
    for (int r = 0; r < 4; r++)
        tile[ty + r * 8][tx] = g_v[(size_t)(b * S_ + s0 + ty + r * 8) * 512 + cb * 32 + tx];
    __syncthreads();

    #pragma unroll
    for (int r = 0; r < 4; r++) {
        int dl = ty + r * 8;
        size_t obase = ((size_t)(b * NKV_ + kvh) * 64 + dbase + dl) * S_;
        g_v2t[obase + s0 + tx] = __float2half_rn(tile[tx][dl]);
    }
}

// ---------------------------------------------------------------------------
// Flash attention on HMMA, f16 2-term splits.
// CTA: 128 q-rows x 64-kv tiles; 8 warps x 16 rows.
// ---------------------------------------------------------------------------
#define KSP   72                        // K/Vt smem stride (f16)
#define PSP   136                       // P smem stride (f16)
#define F_KS  0
#define F_VT  (64 * KSP)
#define F_PS  (2 * 64 * KSP)
#define FLASH_SMEM ((F_PS + 128 * PSP) * 2)   // 53248 bytes

__global__ __launch_bounds__(256) void flash_mma()
{
    extern __shared__ __half smx[];
    __half* Ks = smx + F_KS;     // [64 c][64 kh]
    __half* Vt = smx + F_VT;     // [64 d][64 s]
    __half* Ps = smx + F_PS;     // [128 r][ph64|pl64]

    const int tid  = threadIdx.x;
    const int lane = tid & 31;
    const int wq   = tid >> 5;
    const int g    = lane >> 2;
    const int tq   = lane & 3;

    const int jq  = (gridDim.x - 1) - blockIdx.x;
    const int h   = blockIdx.y;
    const int b   = blockIdx.z;
    const int kvh = h >> 2;
    const int q0  = jq * 128;

    const __half* qbase = g_q2 + ((size_t)(b * NH_ + h) * S_ + q0 + wq * 16) * 128;
    const __half* kbase = g_k2 + (size_t)(b * NKV_ + kvh) * S_ * 64;
    const __half* vbase = g_v2t + (size_t)(b * NKV_ + kvh) * 64 * S_;

    float m0 = -1e30f, m1 = -1e30f, l0 = 0.f, l1 = 0.f;
    float accO[8][4];
    #pragma unroll
    for (int nt = 0; nt < 8; nt++)
        #pragma unroll
        for (int c = 0; c < 4; c++) accO[nt][c] = 0.f;

    const int ntiles = 2 * jq + 2;
    for (int jt = 0; jt < ntiles; jt++) {
        __syncthreads();
        // ---- stage K and Vt tiles (each 64x64 f16) ----
        {
            int r  = tid >> 2, seg = tid & 3;
            const uint4* ksrc = (const uint4*)(kbase + (size_t)(jt * 64 + r) * 64 + seg * 16);
            uint4* kdst = (uint4*)(Ks + r * KSP + seg * 16);
            kdst[0] = ksrc[0]; kdst[1] = ksrc[1];

            const uint4* vsrc = (const uint4*)(vbase + (size_t)r * S_ + jt * 64 + seg * 16);
            uint4* vdst = (uint4*)(Vt + r * KSP + seg * 16);
            vdst[0] = vsrc[0]; vdst[1] = vsrc[1];
        }
        __syncthreads();

        // ---- Q fragments (k-ext 128 = qh|ql), from global (L1-resident) ----
        uint32_t qf[8][4];
        #pragma unroll
        for (int pc = 0; pc < 8; pc++) {
            int c = pc * 16 + tq * 2;
            qf[pc][0] = *(const uint32_t*)(qbase + (size_t)g * 128 + c);
            qf[pc][1] = *(const uint32_t*)(qbase + (size_t)(g + 8) * 128 + c);
            qf[pc][2] = *(const uint32_t*)(qbase + (size_t)g * 128 + c + 8);
            qf[pc][3] = *(const uint32_t*)(qbase + (size_t)(g + 8) * 128 + c + 8);
        }

        // ---- S = (Qh+Ql)(K/8... pre-scaled) : 8 MMAs per nt ----
        float sa[8][4];
        #pragma unroll
        for (int nt = 0; nt < 8; nt++)
            #pragma unroll
            for (int c = 0; c < 4; c++) sa[nt][c] = 0.f;

        #pragma unroll
        for (int kc = 0; kc < 4; kc++) {
            #pragma unroll
            for (int nt = 0; nt < 8; nt++) {
                int n = nt * 8 + g;
                uint32_t bb[2];
                bb[0] = *(const uint32_t*)(Ks + n * KSP + kc * 16 + tq * 2);
                bb[1] = *(const uint32_t*)(Ks + n * KSP + kc * 16 + tq * 2 + 8);
                mma16816(sa[nt], qf[kc],     bb);   // qh * kh
                mma16816(sa[nt], qf[kc + 4], bb);   // ql * kh
            }
        }

        // ---- causal mask ----
        const float NEG = -1e30f;
        if (jt >= 2 * jq) {
            int rg0 = q0 + wq * 16 + g, rg1 = rg0 + 8;
            #pragma unroll
            for (int nt = 0; nt < 8; nt++) {
                int cg = jt * 64 + nt * 8 + tq * 2;
                if (cg     > rg0) sa[nt][0] = NEG;
                if (cg + 1 > rg0) sa[nt][1] = NEG;
                if (cg     > rg1) sa[nt][2] = NEG;
                if (cg + 1 > rg1) sa[nt][3] = NEG;
            }
        }

        // ---- online softmax ----
        float rm0 = NEG, rm1 = NEG;
        #pragma unroll
        for (int nt = 0; nt < 8; nt++) {
            rm0 = fmaxf(rm0, fmaxf(sa[nt][0], sa[nt][1]));
            rm1 = fmaxf(rm1, fmaxf(sa[nt][2], sa[nt][3]));
        }
        rm0 = fmaxf(rm0, __shfl_xor_sync(0xffffffffu, rm0, 1));
        rm0 = fmaxf(rm0, __shfl_xor_sync(0xffffffffu, rm0, 2));
        rm1 = fmaxf(rm1, __shfl_xor_sync(0xffffffffu, rm1, 1));
        rm1 = fmaxf(rm1, __shfl_xor_sync(0xffffffffu, rm1, 2));

        float mn0 = fmaxf(m0, rm0), mn1 = fmaxf(m1, rm1);
        float al0 = __expf(m0 - mn0), al1 = __expf(m1 - mn1);
        m0 = mn0; m1 = mn1;

        float rs0 = 0.f, rs1 = 0.f;
        float p[8][4];
        #pragma unroll
        for (int nt = 0; nt < 8; nt++) {
            p[nt][0] = __expf(sa[nt][0] - mn0);
            p[nt][1] = __expf(sa[nt][1] - mn0);
            p[nt][2] = __expf(sa[nt][2] - mn1);
            p[nt][3] = __expf(sa[nt][3] - mn1);
            rs0 += p[nt][0] + p[nt][1];
            rs1 += p[nt][2] + p[nt][3];
        }
        rs0 += __shfl_xor_sync(0xffffffffu, rs0, 1);
        rs0 += __shfl_xor_sync(0xffffffffu, rs0, 2);
        rs1 += __shfl_xor_sync(0xffffffffu, rs1, 1);
        rs1 += __shfl_xor_sync(0xffffffffu, rs1, 2);
        l0 = l0 * al0 + rs0;
        l1 = l1 * al1 + rs1;

        #pragma unroll
        for (int nt = 0; nt < 8; nt++) {
            accO[nt][0] *= al0; accO[nt][1] *= al0;
            accO[nt][2] *= al1; accO[nt][3] *= al1;
        }

        // ---- P -> smem as [ph | pl] ----
        {
            int pr0 = wq * 16 + g, pr1 = pr0 + 8;
            #pragma unroll
            for (int nt = 0; nt < 8; nt++) {
                int col = nt * 8 + tq * 2;
                float p0 = p[nt][0], p1 = p[nt][1], p2 = p[nt][2], p3 = p[nt][3];
                __half h00 = __float2half_rn(p0), h01 = __float2half_rn(p1);
                __half h10 = __float2half_rn(p2), h11 = __float2half_rn(p3);
                *(uint32_t*)(Ps + pr0 * PSP + col)      = packh(p0, p1);
                *(uint32_t*)(Ps + pr1 * PSP + col)      = packh(p2, p3);
                *(uint32_t*)(Ps + pr0 * PSP + 64 + col) =
                    packh(p0 - __half2float(h00), p1 - __half2float(h01));
                *(uint32_t*)(Ps + pr1 * PSP + 64 + col) =
                    packh(p2 - __half2float(h10), p3 - __half2float(h11));
            }
        }
        __syncthreads();

        // ---- O += (Ph+Pl) Vh : 8 MMAs per nt ----
        uint32_t ap[8][4];
        {
            int pr = wq * 16 + g;
            #pragma unroll
            for (int pc = 0; pc < 8; pc++) {
                int c = pc * 16 + tq * 2;
                ap[pc][0] = *(const uint32_t*)(Ps + pr * PSP + c);
                ap[pc][1] = *(const uint32_t*)(Ps + (pr + 8) * PSP + c);
                ap[pc][2] = *(const uint32_t*)(Ps + pr * PSP + c + 8);
                ap[pc][3] = *(const uint32_t*)(Ps + (pr + 8) * PSP + c + 8);
            }
        }
        #pragma unroll
        for (int vc = 0; vc < 4; vc++) {
            #pragma unroll
            for (int nt = 0; nt < 8; nt++) {
                int n = nt * 8 + g;
                uint32_t bb[2];
                bb[0] = *(const uint32_t*)(Vt + n * KSP + vc * 16 + tq * 2);
                bb[1] = *(const uint32_t*)(Vt + n * KSP + vc * 16 + tq * 2 + 8);
                mma16816(accO[nt], ap[vc],     bb);   // ph * vh
                mma16816(accO[nt], ap[vc + 4], bb);   // pl * vh
            }
        }
    }

    // ---- epilogue: write O' = [hi | lo] into g_a2 ----
    float inv0 = 1.f / l0, inv1 = 1.f / l1;
    size_t r0 = (size_t)b * S_ + q0 + wq * 16 + g;
    #pragma unroll
    for (int nt = 0; nt < 8; nt++) {
        int c = h * 64 + nt * 8 + tq * 2;
        float o00 = accO[nt][0] * inv0, o01 = accO[nt][1] * inv0;
        float o10 = accO[nt][2] * inv1, o11 = accO[nt][3] * inv1;

        __half h00 = __float2half_rn(o00), h01 = __float2half_rn(o01);
        __half h10 = __float2half_rn(o10), h11 = __float2half_rn(o11);

        __half* d0 = g_a2 + r0 * KA_ + c;
        __half* d1 = g_a2 + (r0 + 8) * KA_ + c;
        *(uint32_t*)(d0)        = packh(o00, o01);
        *(uint32_t*)(d0 + 2048) = packh(o00 - __half2float(h00), o01 - __half2float(h01));
        *(uint32_t*)(d1)        = packh(o10, o11);
        *(uint32_t*)(d1 + 2048) = packh(o10 - __half2float(h10), o11 - __half2float(h11));
    }
}

// ---------------------------------------------------------------------------
// launch
// ---------------------------------------------------------------------------
extern "C" void kernel_launch(void* const* d_in, const int* in_sizes, int n_in,
                              void* d_out, int out_size)
{
    const float* X   = (const float*)d_in[0];
    const int*   pos = (const int*)  d_in[1];
    const float* Wq  = (const float*)d_in[2];
    const float* Wk  = (const float*)d_in[3];
    const float* Wv  = (const float*)d_in[4];
    const float* Wo  = (const float*)d_in[5];
    float*       out = (float*)d_out;

    void *pa2, *pwq, *pwk, *pwv, *pwo;
    cudaGetSymbolAddress(&pa2, g_a2);
    cudaGetSymbolAddress(&pwq, g_wq2);
    cudaGetSymbolAddress(&pwk, g_wk2);
    cudaGetSymbolAddress(&pwv, g_wv2);
    cudaGetSymbolAddress(&pwo, g_wo2);

    cudaFuncSetAttribute(flash_mma, cudaFuncAttributeMaxDynamicSharedMemorySize, FLASH_SMEM);

    invfreq_init_kernel<<<1, 32>>>();

    cvt_hilo<<<8192, 256>>>(X, (__half*)pa2);
    cvt_w_T<<<dim3(64, 64), dim3(32, 8)>>>(Wq, (__half*)pwq, 2048);
    cvt_w_T<<<dim3(16, 64), dim3(32, 8)>>>(Wk, (__half*)pwk, 512);
    cvt_w_T<<<dim3(16, 64), dim3(32, 8)>>>(Wv, (__half*)pwv, 512);
    cvt_w_T<<<dim3(64, 64), dim3(32, 8)>>>(Wo, (__half*)pwo, 2048);

    qkv_mma<<<768, 256>>>();

    {
        const int TOT = M_ * (NH_ + NKV_) * 32;
        rope_split_kernel<<<(TOT + 255) / 256, 256>>>(pos);
    }
    cvt_v_kernel<<<dim3(64, 16, 2), dim3(32, 8)>>>();

    flash_mma<<<dim3(S_ / 128, NH_, B_), 256, FLASH_SMEM>>>();

    out_mma<<<512, 256>>>(out);
}

// round 10
// speedup vs baseline: 3.2386x; 1.1620x over previous
#include <cuda_runtime.h>
#include <cuda_fp16.h>
#include <math.h>
#include <cstdint>

#define B_   2
#define S_   2048
#define H_   2048
#define NH_  32
#define NKV_ 8
#define DH_  64
#define M_   (B_*S_)      // 4096 rows
#define KA_  4096         // A' k-ext: [hi | lo]
#define KW_  2048         // W stored once (hi); k-index wraps

typedef unsigned long long u64;

// ---------------------------------------------------------------------------
// Scratch (static device globals; no runtime allocation)
// ---------------------------------------------------------------------------
__device__ float g_q[(size_t)M_ * NH_ * DH_];     // fp32 QKV intermediates
__device__ float g_k[(size_t)M_ * NKV_ * DH_];
__device__ float g_v[(size_t)M_ * NKV_ * DH_];
__device__ float g_invfreq[DH_ / 2];

__device__ __align__(128) __half g_a2 [(size_t)M_   * KA_];  // X'=[hi|lo], then O'
__device__ __align__(128) __half g_wq2[(size_t)2048 * KW_];  // [N,2048] hi only
__device__ __align__(128) __half g_wk2[(size_t)512  * KW_];
__device__ __align__(128) __half g_wv2[(size_t)512  * KW_];
__device__ __align__(128) __half g_wo2[(size_t)2048 * KW_];

// split attention operands
__device__ __align__(128) __half g_q2 [(size_t)B_ * NH_  * S_ * 128]; // [qh64|ql64], pre-scaled 1/8
__device__ __align__(128) __half g_k2 [(size_t)B_ * NKV_ * S_ * 64];  // kh only
__device__ __align__(128) __half g_v2t[(size_t)B_ * NKV_ * 64 * S_];  // [d][s] vh only

// ---------------------------------------------------------------------------
// helpers
// ---------------------------------------------------------------------------
__device__ __forceinline__ void mma16816(float* d, const uint32_t* a, const uint32_t* b) {
    asm volatile("mma.sync.aligned.m16n8k16.row.col.f32.f16.f16.f32 "
                 "{%0,%1,%2,%3}, {%4,%5,%6,%7}, {%8,%9}, {%0,%1,%2,%3};"
                 : "+f"(d[0]), "+f"(d[1]), "+f"(d[2]), "+f"(d[3])
                 : "r"(a[0]), "r"(a[1]), "r"(a[2]), "r"(a[3]), "r"(b[0]), "r"(b[1]));
}
__device__ __forceinline__ uint32_t packh(float a, float b) {
    __half2 p = __halves2half2(__float2half_rn(a), __float2half_rn(b));
    return *(uint32_t*)&p;
}

// ---------------------------------------------------------------------------
// inv_freq init
// ---------------------------------------------------------------------------
__global__ void invfreq_init_kernel() {
    int i = threadIdx.x;
    if (i < DH_ / 2) {
        g_invfreq[i] = (float)(1.0 / pow(10000.0, (double)(2 * i) / (double)DH_));
    }
}

// ---------------------------------------------------------------------------
// hi/lo split: src fp32 [4096, 2048] -> dst f16 [4096, 4096] = [hi|lo]
// ---------------------------------------------------------------------------
__global__ __launch_bounds__(256) void cvt_hilo(const float* __restrict__ src,
                                                __half* __restrict__ dst)
{
    int t = blockIdx.x * blockDim.x + threadIdx.x;
    int m  = t >> 9;
    int c4 = (t & 511) * 4;
    float4 x = *(const float4*)(src + (size_t)m * 2048 + c4);

    __half h0 = __float2half_rn(x.x), h1 = __float2half_rn(x.y);
    __half h2 = __float2half_rn(x.z), h3 = __float2half_rn(x.w);
    __half l0 = __float2half_rn(x.x - __half2float(h0));
    __half l1 = __float2half_rn(x.y - __half2float(h1));
    __half l2 = __float2half_rn(x.z - __half2float(h2));
    __half l3 = __float2half_rn(x.w - __half2float(h3));

    __half2 H01 = __halves2half2(h0, h1), H23 = __halves2half2(h2, h3);
    __half2 L01 = __halves2half2(l0, l1), L23 = __halves2half2(l2, l3);
    uint2 Hv = make_uint2(*(uint32_t*)&H01, *(uint32_t*)&H23);
    uint2 Lv = make_uint2(*(uint32_t*)&L01, *(uint32_t*)&L23);

    size_t base = (size_t)m * KA_ + c4;
    *(uint2*)(dst + base)        = Hv;
    *(uint2*)(dst + base + 2048) = Lv;
}

// ---------------------------------------------------------------------------
// Weight transpose: W fp32 [2048, Nout] -> W' f16 [Nout, 2048] (hi only)
// ---------------------------------------------------------------------------
__global__ __launch_bounds__(256) void cvt_w_T(const float* __restrict__ W,
                                               __half* __restrict__ Wp, int Nout)
{
    __shared__ float tile[32][33];
    int tx = threadIdx.x, ty = threadIdx.y;
    int n0 = blockIdx.x * 32, k0 = blockIdx.y * 32;

    #pragma unroll
    for (int r = 0; r < 4; r++)
        tile[ty + r * 8][tx] = W[(size_t)(k0 + ty + r * 8) * Nout + n0 + tx];
    __syncthreads();

    #pragma unroll
    for (int r = 0; r < 4; r++) {
        int nl = ty + r * 8, kl = tx;
        Wp[(size_t)(n0 + nl) * KW_ + k0 + kl] = __float2half_rn(tile[kl][nl]);
    }
}

// ---------------------------------------------------------------------------
// f16 mma.sync GEMM: C = A'[M,4096] @ W'[N,2048,wrapped]^T
// 128x128 CTA tile, 8 warps (2x4), K-slab 32.
// Prefetch-next-slab pipeline: LDG for slab s+1 issued before compute of s.
// ---------------------------------------------------------------------------
#define KSLAB 32
#define NSLAB (KA_ / KSLAB)     // 128
#define ARS   40

__device__ __forceinline__ void mma_gemm_body(
    const __half* __restrict__ A2, const __half* __restrict__ W2,
    float* __restrict__ C, int Nout, int row0, int col0)
{
    __shared__ __half As[128][ARS];
    __shared__ __half Bs[128][ARS];

    const int tid  = threadIdx.x;
    const int lane = tid & 31;
    const int wid  = tid >> 5;
    const int wm   = wid >> 2;
    const int wn   = wid & 3;
    const int g    = lane >> 2;
    const int tq   = lane & 3;

    const int lrow = tid >> 2;
    const int lk   = (tid & 3) * 8;

    const __half* Ag = A2 + (size_t)(row0 + lrow) * KA_ + lk;
    const __half* Bg = W2 + (size_t)(col0 + lrow) * KW_ + lk;

    float acc[4][4][4];
    #pragma unroll
    for (int i = 0; i < 4; i++)
        #pragma unroll
        for (int j = 0; j < 4; j++)
            #pragma unroll
            for (int c = 0; c < 4; c++) acc[i][j][c] = 0.f;

    // preload slab 0 and commit to smem
    uint4 a0 = *(const uint4*)(Ag);
    uint4 a1 = *(const uint4*)(Ag + (size_t)64 * KA_);
    uint4 b0 = *(const uint4*)(Bg);
    uint4 b1 = *(const uint4*)(Bg + (size_t)64 * KW_);
    *(uint4*)&As[lrow][lk]      = a0;
    *(uint4*)&As[lrow + 64][lk] = a1;
    *(uint4*)&Bs[lrow][lk]      = b0;
    *(uint4*)&Bs[lrow + 64][lk] = b1;
    __syncthreads();

    for (int s = 0; s < NSLAB; s++) {
        const bool more = (s + 1 < NSLAB);
        if (more) {   // prefetch NEXT slab; latency hidden behind compute below
            const int ka = (s + 1) * KSLAB;
            const int kw = ka & (KW_ - 1);
            a0 = *(const uint4*)(Ag + ka);
            a1 = *(const uint4*)(Ag + ka + (size_t)64 * KA_);
            b0 = *(const uint4*)(Bg + kw);
            b1 = *(const uint4*)(Bg + kw + (size_t)64 * KW_);
        }

        #pragma unroll
        for (int ks = 0; ks < 2; ks++) {
            const int c0 = tq * 2 + ks * 16;
            uint32_t af[4][4];
            #pragma unroll
            for (int mt = 0; mt < 4; mt++) {
                const int r = wm * 64 + mt * 16 + g;
                af[mt][0] = *(const uint32_t*)&As[r][c0];
                af[mt][1] = *(const uint32_t*)&As[r + 8][c0];
                af[mt][2] = *(const uint32_t*)&As[r][c0 + 8];
                af[mt][3] = *(const uint32_t*)&As[r + 8][c0 + 8];
            }
            uint32_t bf[4][2];
            #pragma unroll
            for (int nt = 0; nt < 4; nt++) {
                const int n = wn * 32 + nt * 8 + g;
                bf[nt][0] = *(const uint32_t*)&Bs[n][c0];
                bf[nt][1] = *(const uint32_t*)&Bs[n][c0 + 8];
            }
            #pragma unroll
            for (int mt = 0; mt < 4; mt++)
                #pragma unroll
                for (int nt = 0; nt < 4; nt++)
                    mma16816(acc[mt][nt], af[mt], bf[nt]);
        }

        if (more) {
            __syncthreads();
            *(uint4*)&As[lrow][lk]      = a0;
            *(uint4*)&As[lrow + 64][lk] = a1;
            *(uint4*)&Bs[lrow][lk]      = b0;
            *(uint4*)&Bs[lrow + 64][lk] = b1;
            __syncthreads();
        }
    }

    #pragma unroll
    for (int mt = 0; mt < 4; mt++) {
        #pragma unroll
        for (int nt = 0; nt < 4; nt++) {
            int row = row0 + wm * 64 + mt * 16 + g;
            int col = col0 + wn * 32 + nt * 8 + tq * 2;
            *(float2*)&C[(size_t)row * Nout + col] =
                make_float2(acc[mt][nt][0], acc[mt][nt][1]);
            *(float2*)&C[(size_t)(row + 8) * Nout + col] =
                make_float2(acc[mt][nt][2], acc[mt][nt][3]);
        }
    }
}

__global__ __launch_bounds__(256, 2) void qkv_mma()
{
    const int bx = blockIdx.x;
    if (bx < 512)
        mma_gemm_body(g_a2, g_wq2, g_q, NH_ * DH_, (bx >> 4) * 128, (bx & 15) * 128);
    else if (bx < 640) {
        int t = bx - 512;
        mma_gemm_body(g_a2, g_wk2, g_k, NKV_ * DH_, (t >> 2) * 128, (t & 3) * 128);
    } else {
        int t = bx - 640;
        mma_gemm_body(g_a2, g_wv2, g_v, NKV_ * DH_, (t >> 2) * 128, (t & 3) * 128);
    }
}

__global__ __launch_bounds__(256, 2) void out_mma(float* __restrict__ out)
{
    const int bx = blockIdx.x;
    mma_gemm_body(g_a2, g_wo2, out, H_, (bx >> 4) * 128, (bx & 15) * 128);
}

// ---------------------------------------------------------------------------
// RoPE + split: g_q -> g_q2 [qh|ql] scaled 1/8 ; g_k -> g_k2 [kh] only
// ---------------------------------------------------------------------------
__global__ __launch_bounds__(256) void rope_split_kernel(const int* __restrict__ pos_ids)
{
    const int TOT = M_ * (NH_ + NKV_) * 32;
    int t = blockIdx.x * blockDim.x + threadIdx.x;
    if (t >= TOT) return;

    int i  = t & 31;
    int h  = (t >> 5) % (NH_ + NKV_);
    int bs = t / (32 * (NH_ + NKV_));
    int b  = bs >> 11, s = bs & 2047;

    float pos = (float)pos_ids[bs];
    float f = pos * g_invfreq[i];
    float sn, c;
    sincosf(f, &sn, &c);

    if (h < NH_) {
        const float* base = g_q + (size_t)bs * (NH_ * DH_) + h * DH_;
        __half* dst = g_q2 + ((size_t)(b * NH_ + h) * S_ + s) * 128;
        float x1 = base[i], x2 = base[i + 32];
        float o1 = (x1 * c - x2 * sn) * 0.125f;
        float o2 = (x2 * c + x1 * sn) * 0.125f;
        __half h1 = __float2half_rn(o1);
        __half h2 = __float2half_rn(o2);
        dst[i]           = h1;
        dst[i + 32]      = h2;
        dst[64 + i]      = __float2half_rn(o1 - __half2float(h1));
        dst[64 + i + 32] = __float2half_rn(o2 - __half2float(h2));
    } else {
        const float* base = g_k + (size_t)bs * (NKV_ * DH_) + (h - NH_) * DH_;
        __half* dst = g_k2 + ((size_t)(b * NKV_ + (h - NH_)) * S_ + s) * 64;
        float x1 = base[i], x2 = base[i + 32];
        dst[i]      = __float2half_rn(x1 * c - x2 * sn);
        dst[i + 32] = __float2half_rn(x2 * c + x1 * sn);
    }
}

// ---------------------------------------------------------------------------
// V transpose: g_v fp32 [m][512] -> g_v2t f16 [b][kvh][d][s] (hi only)
// ---------------------------------------------------------------------------
__global__ __launch_bounds__(256) void cvt_v_kernel()
{
    __shared__ float tile[32][33];
    int tx = threadIdx.x, ty = threadIdx.y;
    int s0 = blockIdx.x * 32;
    int cb = blockIdx.y;
    int b  = blockIdx.z;
    int kvh = cb >> 1, dbase = (cb & 1) * 32;

    #pragma unroll
    for (int r = 0; r < 4; r++)
        tile[ty + r * 8][tx] = g_v[(size_t)(b * S_ + s0 + ty + r * 8) * 512 + cb * 32 + tx];
    __syncthreads();

    #pragma unroll
    for (int r = 0; r < 4; r++) {
        int dl = ty + r * 8;
        size_t obase = ((size_t)(b * NKV_ + kvh) * 64 + dbase + dl) * S_;
        g_v2t[obase + s0 + tx] = __float2half_rn(tile[tx][dl]);
    }
}

// ---------------------------------------------------------------------------
// Flash attention on HMMA, f16 2-term splits.
// CTA: 128 q-rows x 64-kv tiles; 8 warps x 16 rows.
// P stays in registers (QK accumulator fragment == PV A-operand fragment).
// Q fragments hoisted out of the KV loop.
// ---------------------------------------------------------------------------
#define KSP   72                        // K/Vt smem stride (f16)

__global__ __launch_bounds__(256) void flash_mma()
{
    __shared__ __half Ks[64 * KSP];     // [64 c][64 kh]
    __shared__ __half Vt[64 * KSP];     // [64 d][64 s]

    const int tid  = threadIdx.x;
    const int lane = tid & 31;
    const int wq   = tid >> 5;
    const int g    = lane >> 2;
    const int tq   = lane & 3;

    const int jq  = (gridDim.x - 1) - blockIdx.x;
    const int h   = blockIdx.y;
    const int b   = blockIdx.z;
    const int kvh = h >> 2;
    const int q0  = jq * 128;

    const __half* qbase = g_q2 + ((size_t)(b * NH_ + h) * S_ + q0 + wq * 16) * 128;
    const __half* kbase = g_k2 + (size_t)(b * NKV_ + kvh) * S_ * 64;
    const __half* vbase = g_v2t + (size_t)(b * NKV_ + kvh) * 64 * S_;

    // ---- Q fragments: loop-invariant, load once ----
    uint32_t qf[8][4];
    #pragma unroll
    for (int pc = 0; pc < 8; pc++) {
        int c = pc * 16 + tq * 2;
        qf[pc][0] = *(const uint32_t*)(qbase + (size_t)g * 128 + c);
        qf[pc][1] = *(const uint32_t*)(qbase + (size_t)(g + 8) * 128 + c);
        qf[pc][2] = *(const uint32_t*)(qbase + (size_t)g * 128 + c + 8);
        qf[pc][3] = *(const uint32_t*)(qbase + (size_t)(g + 8) * 128 + c + 8);
    }

    float m0 = -1e30f, m1 = -1e30f, l0 = 0.f, l1 = 0.f;
    float accO[8][4];
    #pragma unroll
    for (int nt = 0; nt < 8; nt++)
        #pragma unroll
        for (int c = 0; c < 4; c++) accO[nt][c] = 0.f;

    const int ntiles = 2 * jq + 2;
    for (int jt = 0; jt < ntiles; jt++) {
        __syncthreads();    // prior tile's PV reads of Ks/Vt done
        // ---- stage K and Vt tiles (each 64x64 f16) ----
        {
            int r  = tid >> 2, seg = tid & 3;
            const uint4* ksrc = (const uint4*)(kbase + (size_t)(jt * 64 + r) * 64 + seg * 16);
            uint4* kdst = (uint4*)(Ks + r * KSP + seg * 16);
            kdst[0] = ksrc[0]; kdst[1] = ksrc[1];

            const uint4* vsrc = (const uint4*)(vbase + (size_t)r * S_ + jt * 64 + seg * 16);
            uint4* vdst = (uint4*)(Vt + r * KSP + seg * 16);
            vdst[0] = vsrc[0]; vdst[1] = vsrc[1];
        }
        __syncthreads();

        // ---- S = (Qh+Ql) Kh ----
        float sa[8][4];
        #pragma unroll
        for (int nt = 0; nt < 8; nt++)
            #pragma unroll
            for (int c = 0; c < 4; c++) sa[nt][c] = 0.f;

        #pragma unroll
        for (int kc = 0; kc < 4; kc++) {
            #pragma unroll
            for (int nt = 0; nt < 8; nt++) {
                int n = nt * 8 + g;
                uint32_t bb[2];
                bb[0] = *(const uint32_t*)(Ks + n * KSP + kc * 16 + tq * 2);
                bb[1] = *(const uint32_t*)(Ks + n * KSP + kc * 16 + tq * 2 + 8);
                mma16816(sa[nt], qf[kc],     bb);   // qh * kh
                mma16816(sa[nt], qf[kc + 4], bb);   // ql * kh
            }
        }

        // ---- causal mask ----
        const float NEG = -1e30f;
        if (jt >= 2 * jq) {
            int rg0 = q0 + wq * 16 + g, rg1 = rg0 + 8;
            #pragma unroll
            for (int nt = 0; nt < 8; nt++) {
                int cg = jt * 64 + nt * 8 + tq * 2;
                if (cg     > rg0) sa[nt][0] = NEG;
                if (cg + 1 > rg0) sa[nt][1] = NEG;
                if (cg     > rg1) sa[nt][2] = NEG;
                if (cg + 1 > rg1) sa[nt][3] = NEG;
            }
        }

        // ---- online softmax ----
        float rm0 = NEG, rm1 = NEG;
        #pragma unroll
        for (int nt = 0; nt < 8; nt++) {
            rm0 = fmaxf(rm0, fmaxf(sa[nt][0], sa[nt][1]));
            rm1 = fmaxf(rm1, fmaxf(sa[nt][2], sa[nt][3]));
        }
        rm0 = fmaxf(rm0, __shfl_xor_sync(0xffffffffu, rm0, 1));
        rm0 = fmaxf(rm0, __shfl_xor_sync(0xffffffffu, rm0, 2));
        rm1 = fmaxf(rm1, __shfl_xor_sync(0xffffffffu, rm1, 1));
        rm1 = fmaxf(rm1, __shfl_xor_sync(0xffffffffu, rm1, 2));

        float mn0 = fmaxf(m0, rm0), mn1 = fmaxf(m1, rm1);
        float al0 = __expf(m0 - mn0), al1 = __expf(m1 - mn1);
        m0 = mn0; m1 = mn1;

        float rs0 = 0.f, rs1 = 0.f;
        float p[8][4];
        #pragma unroll
        for (int nt = 0; nt < 8; nt++) {
            p[nt][0] = __expf(sa[nt][0] - mn0);
            p[nt][1] = __expf(sa[nt][1] - mn0);
            p[nt][2] = __expf(sa[nt][2] - mn1);
            p[nt][3] = __expf(sa[nt][3] - mn1);
            rs0 += p[nt][0] + p[nt][1];
            rs1 += p[nt][2] + p[nt][3];
        }
        rs0 += __shfl_xor_sync(0xffffffffu, rs0, 1);
        rs0 += __shfl_xor_sync(0xffffffffu, rs0, 2);
        rs1 += __shfl_xor_sync(0xffffffffu, rs1, 1);
        rs1 += __shfl_xor_sync(0xffffffffu, rs1, 2);
        l0 = l0 * al0 + rs0;
        l1 = l1 * al1 + rs1;

        #pragma unroll
        for (int nt = 0; nt < 8; nt++) {
            accO[nt][0] *= al0; accO[nt][1] *= al0;
            accO[nt][2] *= al1; accO[nt][3] *= al1;
        }

        // ---- build PV A-fragments directly from registers ----
        // A-frag for k-chunk kc: a0=(g, kc*16+2tq) a1=(g+8, same) a2=(g, +8) a3=(g+8, +8)
        // col kc*16+2tq  == n-tile 2kc   cols 2tq..  -> p[2kc][0..1] / [2..3]
        // col kc*16+8+2tq== n-tile 2kc+1 cols 2tq..  -> p[2kc+1][..]
        uint32_t aph[4][4], apl[4][4];
        #pragma unroll
        for (int kc = 0; kc < 4; kc++) {
            float p00 = p[2*kc][0],   p01 = p[2*kc][1];
            float p02 = p[2*kc][2],   p03 = p[2*kc][3];
            float p10 = p[2*kc+1][0], p11 = p[2*kc+1][1];
            float p12 = p[2*kc+1][2], p13 = p[2*kc+1][3];
            aph[kc][0] = packh(p00, p01);
            aph[kc][1] = packh(p02, p03);
            aph[kc][2] = packh(p10, p11);
            aph[kc][3] = packh(p12, p13);
            apl[kc][0] = packh(p00 - __half2float(__float2half_rn(p00)),
                               p01 - __half2float(__float2half_rn(p01)));
            apl[kc][1] = packh(p02 - __half2float(__float2half_rn(p02)),
                               p03 - __half2float(__float2half_rn(p03)));
            apl[kc][2] = packh(p10 - __half2float(__float2half_rn(p10)),
                               p11 - __half2float(__float2half_rn(p11)));
            apl[kc][3] = packh(p12 - __half2float(__float2half_rn(p12)),
                               p13 - __half2float(__float2half_rn(p13)));
        }

        // ---- O += (Ph+Pl) Vh ----
        #pragma unroll
        for (int vc = 0; vc < 4; vc++) {
            #pragma unroll
            for (int nt = 0; nt < 8; nt++) {
                int n = nt * 8 + g;
                uint32_t bb[2];
                bb[0] = *(const uint32_t*)(Vt + n * KSP + vc * 16 + tq * 2);
                bb[1] = *(const uint32_t*)(Vt + n * KSP + vc * 16 + tq * 2 + 8);
                mma16816(accO[nt], aph[vc], bb);   // ph * vh
                mma16816(accO[nt], apl[vc], bb);   // pl * vh
            }
        }
    }

    // ---- epilogue: write O' = [hi | lo] into g_a2 ----
    float inv0 = 1.f / l0, inv1 = 1.f / l1;
    size_t r0 = (size_t)b * S_ + q0 + wq * 16 + g;
    #pragma unroll
    for (int nt = 0; nt < 8; nt++) {
        int c = h * 64 + nt * 8 + tq * 2;
        float o00 = accO[nt][0] * inv0, o01 = accO[nt][1] * inv0;
        float o10 = accO[nt][2] * inv1, o11 = accO[nt][3] * inv1;

        __half h00 = __float2half_rn(o00), h01 = __float2half_rn(o01);
        __half h10 = __float2half_rn(o10), h11 = __float2half_rn(o11);

        __half* d0 = g_a2 + r0 * KA_ + c;
        __half* d1 = g_a2 + (r0 + 8) * KA_ + c;
        *(uint32_t*)(d0)        = packh(o00, o01);
        *(uint32_t*)(d0 + 2048) = packh(o00 - __half2float(h00), o01 - __half2float(h01));
        *(uint32_t*)(d1)        = packh(o10, o11);
        *(uint32_t*)(d1 + 2048) = packh(o10 - __half2float(h10), o11 - __half2float(h11));
    }
}

// ---------------------------------------------------------------------------
// launch
// ---------------------------------------------------------------------------
extern "C" void kernel_launch(void* const* d_in, const int* in_sizes, int n_in,
                              void* d_out, int out_size)
{
    const float* X   = (const float*)d_in[0];
    const int*   pos = (const int*)  d_in[1];
    const float* Wq  = (const float*)d_in[2];
    const float* Wk  = (const float*)d_in[3];
    const float* Wv  = (const float*)d_in[4];
    const float* Wo  = (const float*)d_in[5];
    float*       out = (float*)d_out;

    void *pa2, *pwq, *pwk, *pwv, *pwo;
    cudaGetSymbolAddress(&pa2, g_a2);
    cudaGetSymbolAddress(&pwq, g_wq2);
    cudaGetSymbolAddress(&pwk, g_wk2);
    cudaGetSymbolAddress(&pwv, g_wv2);
    cudaGetSymbolAddress(&pwo, g_wo2);

    invfreq_init_kernel<<<1, 32>>>();

    cvt_hilo<<<8192, 256>>>(X, (__half*)pa2);
    cvt_w_T<<<dim3(64, 64), dim3(32, 8)>>>(Wq, (__half*)pwq, 2048);
    cvt_w_T<<<dim3(16, 64), dim3(32, 8)>>>(Wk, (__half*)pwk, 512);
    cvt_w_T<<<dim3(16, 64), dim3(32, 8)>>>(Wv, (__half*)pwv, 512);
    cvt_w_T<<<dim3(64, 64), dim3(32, 8)>>>(Wo, (__half*)pwo, 2048);

    qkv_mma<<<768, 256>>>();

    {
        const int TOT = M_ * (NH_ + NKV_) * 32;
        rope_split_kernel<<<(TOT + 255) / 256, 256>>>(pos);
    }
    cvt_v_kernel<<<dim3(64, 16, 2), dim3(32, 8)>>>();

    flash_mma<<<dim3(S_ / 128, NH_, B_), 256>>>();

    out_mma<<<512, 256>>>(out);
}

// round 11
// speedup vs baseline: 3.7468x; 1.1569x over previous
#include <cuda_runtime.h>
#include <cuda_fp16.h>
#include <math.h>
#include <cstdint>

#define B_   2
#define S_   2048
#define H_   2048
#define NH_  32
#define NKV_ 8
#define DH_  64
#define M_   (B_*S_)      // 4096 rows
#define KA_  4096         // A' k-ext: [hi | lo]
#define KW_  2048         // W stored once (hi); k-index wraps

typedef unsigned long long u64;

// ---------------------------------------------------------------------------
// Scratch (static device globals; no runtime allocation)
// ---------------------------------------------------------------------------
__device__ float g_q[(size_t)M_ * NH_ * DH_];     // fp32 QKV intermediates
__device__ float g_k[(size_t)M_ * NKV_ * DH_];
__device__ float g_v[(size_t)M_ * NKV_ * DH_];
__device__ float g_invfreq[DH_ / 2];

__device__ __align__(128) __half g_a2 [(size_t)M_   * KA_];  // X'=[hi|lo], then O'
__device__ __align__(128) __half g_wq2[(size_t)2048 * KW_];  // [N,2048] hi only
__device__ __align__(128) __half g_wk2[(size_t)512  * KW_];
__device__ __align__(128) __half g_wv2[(size_t)512  * KW_];
__device__ __align__(128) __half g_wo2[(size_t)2048 * KW_];

// split attention operands
__device__ __align__(128) __half g_q2 [(size_t)B_ * NH_  * S_ * 128]; // [qh64|ql64], pre-scaled 1/8
__device__ __align__(128) __half g_k2 [(size_t)B_ * NKV_ * S_ * 64];  // kh only
__device__ __align__(128) __half g_v2t[(size_t)B_ * NKV_ * 64 * S_];  // [d][s] vh only

// ---------------------------------------------------------------------------
// helpers
// ---------------------------------------------------------------------------
__device__ __forceinline__ void mma16816(float* d, const uint32_t* a, const uint32_t* b) {
    asm volatile("mma.sync.aligned.m16n8k16.row.col.f32.f16.f16.f32 "
                 "{%0,%1,%2,%3}, {%4,%5,%6,%7}, {%8,%9}, {%0,%1,%2,%3};"
                 : "+f"(d[0]), "+f"(d[1]), "+f"(d[2]), "+f"(d[3])
                 : "r"(a[0]), "r"(a[1]), "r"(a[2]), "r"(a[3]), "r"(b[0]), "r"(b[1]));
}
__device__ __forceinline__ uint32_t packh(float a, float b) {
    __half2 p = __halves2half2(__float2half_rn(a), __float2half_rn(b));
    return *(uint32_t*)&p;
}
__device__ __forceinline__ uint32_t smem_u32(const void* p) {
    uint32_t a;
    asm("{ .reg .u64 t; cvta.to.shared.u64 t, %1; cvt.u32.u64 %0, t; }" : "=r"(a) : "l"(p));
    return a;
}
__device__ __forceinline__ void ldmx4(uint32_t& r0, uint32_t& r1, uint32_t& r2, uint32_t& r3,
                                      uint32_t a) {
    asm volatile("ldmatrix.sync.aligned.m8n8.x4.shared.b16 {%0,%1,%2,%3}, [%4];"
                 : "=r"(r0), "=r"(r1), "=r"(r2), "=r"(r3) : "r"(a));
}

// ---------------------------------------------------------------------------
// inv_freq init
// ---------------------------------------------------------------------------
__global__ void invfreq_init_kernel() {
    int i = threadIdx.x;
    if (i < DH_ / 2) {
        g_invfreq[i] = (float)(1.0 / pow(10000.0, (double)(2 * i) / (double)DH_));
    }
}

// ---------------------------------------------------------------------------
// hi/lo split: src fp32 [4096, 2048] -> dst f16 [4096, 4096] = [hi|lo]
// ---------------------------------------------------------------------------
__global__ __launch_bounds__(256) void cvt_hilo(const float* __restrict__ src,
                                                __half* __restrict__ dst)
{
    int t = blockIdx.x * blockDim.x + threadIdx.x;
    int m  = t >> 9;
    int c4 = (t & 511) * 4;
    float4 x = *(const float4*)(src + (size_t)m * 2048 + c4);

    __half h0 = __float2half_rn(x.x), h1 = __float2half_rn(x.y);
    __half h2 = __float2half_rn(x.z), h3 = __float2half_rn(x.w);
    __half l0 = __float2half_rn(x.x - __half2float(h0));
    __half l1 = __float2half_rn(x.y - __half2float(h1));
    __half l2 = __float2half_rn(x.z - __half2float(h2));
    __half l3 = __float2half_rn(x.w - __half2float(h3));

    __half2 H01 = __halves2half2(h0, h1), H23 = __halves2half2(h2, h3);
    __half2 L01 = __halves2half2(l0, l1), L23 = __halves2half2(l2, l3);
    uint2 Hv = make_uint2(*(uint32_t*)&H01, *(uint32_t*)&H23);
    uint2 Lv = make_uint2(*(uint32_t*)&L01, *(uint32_t*)&L23);

    size_t base = (size_t)m * KA_ + c4;
    *(uint2*)(dst + base)        = Hv;
    *(uint2*)(dst + base + 2048) = Lv;
}

// ---------------------------------------------------------------------------
// Weight transpose: W fp32 [2048, Nout] -> W' f16 [Nout, 2048] (hi only)
// ---------------------------------------------------------------------------
__global__ __launch_bounds__(256) void cvt_w_T(const float* __restrict__ W,
                                               __half* __restrict__ Wp, int Nout)
{
    __shared__ float tile[32][33];
    int tx = threadIdx.x, ty = threadIdx.y;
    int n0 = blockIdx.x * 32, k0 = blockIdx.y * 32;

    #pragma unroll
    for (int r = 0; r < 4; r++)
        tile[ty + r * 8][tx] = W[(size_t)(k0 + ty + r * 8) * Nout + n0 + tx];
    __syncthreads();

    #pragma unroll
    for (int r = 0; r < 4; r++) {
        int nl = ty + r * 8, kl = tx;
        Wp[(size_t)(n0 + nl) * KW_ + k0 + kl] = __float2half_rn(tile[kl][nl]);
    }
}

// ---------------------------------------------------------------------------
// f16 mma.sync GEMM: C = A'[M,4096] @ W'[N,2048,wrapped]^T
// 128x128 CTA tile, 8 warps (2x4), K-slab 32, double-buffered smem,
// ldmatrix fragment loads, prefetch-next-slab.
// ---------------------------------------------------------------------------
#define KSLAB 32
#define NSLAB (KA_ / KSLAB)     // 128
#define ARS   40                // smem row stride in halves (80 B)

__device__ __forceinline__ void mma_gemm_body(
    const __half* __restrict__ A2, const __half* __restrict__ W2,
    float* __restrict__ C, int Nout, int row0, int col0)
{
    __shared__ __half As[2][128][ARS];   // 2 x 10 KB
    __shared__ __half Bs[2][128][ARS];

    const int tid  = threadIdx.x;
    const int lane = tid & 31;
    const int wid  = tid >> 5;
    const int wm   = wid >> 2;
    const int wn   = wid & 3;
    const int g    = lane >> 2;
    const int tq   = lane & 3;

    const int lrow = tid >> 2;
    const int lk   = (tid & 3) * 8;

    const __half* Ag = A2 + (size_t)(row0 + lrow) * KA_ + lk;
    const __half* Bg = W2 + (size_t)(col0 + lrow) * KW_ + lk;

    // ldmatrix base addresses per buffer
    const uint32_t AROW = ARS * 2;       // bytes per smem row
    uint32_t aB[2], bB[2];
    #pragma unroll
    for (int u = 0; u < 2; u++) {
        aB[u] = smem_u32(&As[u][wm * 64 + (lane & 15)][(lane >> 4) * 8]);
        bB[u] = smem_u32(&Bs[u][wn * 32 + (lane >> 4) * 8 + (lane & 7)][((lane >> 3) & 1) * 8]);
    }

    float acc[4][4][4];
    #pragma unroll
    for (int i = 0; i < 4; i++)
        #pragma unroll
        for (int j = 0; j < 4; j++)
            #pragma unroll
            for (int c = 0; c < 4; c++) acc[i][j][c] = 0.f;

    // preload slab 0 into buffer 0
    uint4 a0 = *(const uint4*)(Ag);
    uint4 a1 = *(const uint4*)(Ag + (size_t)64 * KA_);
    uint4 b0 = *(const uint4*)(Bg);
    uint4 b1 = *(const uint4*)(Bg + (size_t)64 * KW_);
    *(uint4*)&As[0][lrow][lk]      = a0;
    *(uint4*)&As[0][lrow + 64][lk] = a1;
    *(uint4*)&Bs[0][lrow][lk]      = b0;
    *(uint4*)&Bs[0][lrow + 64][lk] = b1;
    __syncthreads();

    int buf = 0;
    for (int s = 0; s < NSLAB; s++) {
        const bool more = (s + 1 < NSLAB);
        if (more) {   // prefetch next slab (latency hidden behind MMAs below)
            const int ka = (s + 1) * KSLAB;
            const int kw = ka & (KW_ - 1);
            a0 = *(const uint4*)(Ag + ka);
            a1 = *(const uint4*)(Ag + ka + (size_t)64 * KA_);
            b0 = *(const uint4*)(Bg + kw);
            b1 = *(const uint4*)(Bg + kw + (size_t)64 * KW_);
        }

        #pragma unroll
        for (int ks = 0; ks < 2; ks++) {
            uint32_t af[4][4];
            #pragma unroll
            for (int mt = 0; mt < 4; mt++)
                ldmx4(af[mt][0], af[mt][1], af[mt][2], af[mt][3],
                      aB[buf] + (uint32_t)(mt * 16) * AROW + ks * 32);
            uint32_t bf[4][2];
            ldmx4(bf[0][0], bf[0][1], bf[1][0], bf[1][1], bB[buf] + ks * 32);
            ldmx4(bf[2][0], bf[2][1], bf[3][0], bf[3][1],
                  bB[buf] + (uint32_t)16 * AROW + ks * 32);

            #pragma unroll
            for (int mt = 0; mt < 4; mt++)
                #pragma unroll
                for (int nt = 0; nt < 4; nt++)
                    mma16816(acc[mt][nt], af[mt], bf[nt]);
        }

        if (more) {
            const int nb = buf ^ 1;   // last read one sync ago -> safe to fill
            *(uint4*)&As[nb][lrow][lk]      = a0;
            *(uint4*)&As[nb][lrow + 64][lk] = a1;
            *(uint4*)&Bs[nb][lrow][lk]      = b0;
            *(uint4*)&Bs[nb][lrow + 64][lk] = b1;
            __syncthreads();
            buf = nb;
        }
    }

    #pragma unroll
    for (int mt = 0; mt < 4; mt++) {
        #pragma unroll
        for (int nt = 0; nt < 4; nt++) {
            int row = row0 + wm * 64 + mt * 16 + g;
            int col = col0 + wn * 32 + nt * 8 + tq * 2;
            *(float2*)&C[(size_t)row * Nout + col] =
                make_float2(acc[mt][nt][0], acc[mt][nt][1]);
            *(float2*)&C[(size_t)(row + 8) * Nout + col] =
                make_float2(acc[mt][nt][2], acc[mt][nt][3]);
        }
    }
}

__global__ __launch_bounds__(256, 2) void qkv_mma()
{
    const int bx = blockIdx.x;
    if (bx < 512)
        mma_gemm_body(g_a2, g_wq2, g_q, NH_ * DH_, (bx >> 4) * 128, (bx & 15) * 128);
    else if (bx < 640) {
        int t = bx - 512;
        mma_gemm_body(g_a2, g_wk2, g_k, NKV_ * DH_, (t >> 2) * 128, (t & 3) * 128);
    } else {
        int t = bx - 640;
        mma_gemm_body(g_a2, g_wv2, g_v, NKV_ * DH_, (t >> 2) * 128, (t & 3) * 128);
    }
}

__global__ __launch_bounds__(256, 2) void out_mma(float* __restrict__ out)
{
    const int bx = blockIdx.x;
    mma_gemm_body(g_a2, g_wo2, out, H_, (bx >> 4) * 128, (bx & 15) * 128);
}

// ---------------------------------------------------------------------------
// RoPE + split: g_q -> g_q2 [qh|ql] scaled 1/8 ; g_k -> g_k2 [kh] only
// ---------------------------------------------------------------------------
__global__ __launch_bounds__(256) void rope_split_kernel(const int* __restrict__ pos_ids)
{
    const int TOT = M_ * (NH_ + NKV_) * 32;
    int t = blockIdx.x * blockDim.x + threadIdx.x;
    if (t >= TOT) return;

    int i  = t & 31;
    int h  = (t >> 5) % (NH_ + NKV_);
    int bs = t / (32 * (NH_ + NKV_));
    int b  = bs >> 11, s = bs & 2047;

    float pos = (float)pos_ids[bs];
    float f = pos * g_invfreq[i];
    float sn, c;
    sincosf(f, &sn, &c);

    if (h < NH_) {
        const float* base = g_q + (size_t)bs * (NH_ * DH_) + h * DH_;
        __half* dst = g_q2 + ((size_t)(b * NH_ + h) * S_ + s) * 128;
        float x1 = base[i], x2 = base[i + 32];
        float o1 = (x1 * c - x2 * sn) * 0.125f;
        float o2 = (x2 * c + x1 * sn) * 0.125f;
        __half h1 = __float2half_rn(o1);
        __half h2 = __float2half_rn(o2);
        dst[i]           = h1;
        dst[i + 32]      = h2;
        dst[64 + i]      = __float2half_rn(o1 - __half2float(h1));
        dst[64 + i + 32] = __float2half_rn(o2 - __half2float(h2));
    } else {
        const float* base = g_k + (size_t)bs * (NKV_ * DH_) + (h - NH_) * DH_;
        __half* dst = g_k2 + ((size_t)(b * NKV_ + (h - NH_)) * S_ + s) * 64;
        float x1 = base[i], x2 = base[i + 32];
        dst[i]      = __float2half_rn(x1 * c - x2 * sn);
        dst[i + 32] = __float2half_rn(x2 * c + x1 * sn);
    }
}

// ---------------------------------------------------------------------------
// V transpose: g_v fp32 [m][512] -> g_v2t f16 [b][kvh][d][s] (hi only)
// ---------------------------------------------------------------------------
__global__ __launch_bounds__(256) void cvt_v_kernel()
{
    __shared__ float tile[32][33];
    int tx = threadIdx.x, ty = threadIdx.y;
    int s0 = blockIdx.x * 32;
    int cb = blockIdx.y;
    int b  = blockIdx.z;
    int kvh = cb >> 1, dbase = (cb & 1) * 32;

    #pragma unroll
    for (int r = 0; r < 4; r++)
        tile[ty + r * 8][tx] = g_v[(size_t)(b * S_ + s0 + ty + r * 8) * 512 + cb * 32 + tx];
    __syncthreads();

    #pragma unroll
    for (int r = 0; r < 4; r++) {
        int dl = ty + r * 8;
        size_t obase = ((size_t)(b * NKV_ + kvh) * 64 + dbase + dl) * S_;
        g_v2t[obase + s0 + tx] = __float2half_rn(tile[tx][dl]);
    }
}

// ---------------------------------------------------------------------------
// Flash attention on HMMA, f16 2-term splits.
// CTA: 128 q-rows x 64-kv tiles; 8 warps x 16 rows.
// ldmatrix operand loads; double-buffered K/V tiles with global prefetch;
// P stays in registers.
// ---------------------------------------------------------------------------
#define KSP   72                        // K/Vt smem stride (f16)

__global__ __launch_bounds__(256) void flash_mma()
{
    __shared__ __half Ks[2][64 * KSP];
    __shared__ __half Vt[2][64 * KSP];

    const int tid  = threadIdx.x;
    const int lane = tid & 31;
    const int wq   = tid >> 5;
    const int g    = lane >> 2;
    const int tq   = lane & 3;

    const int jq  = (gridDim.x - 1) - blockIdx.x;
    const int h   = blockIdx.y;
    const int b   = blockIdx.z;
    const int kvh = h >> 2;
    const int q0  = jq * 128;

    const __half* qbase = g_q2 + ((size_t)(b * NH_ + h) * S_ + q0 + wq * 16) * 128;
    const __half* kbase = g_k2 + (size_t)(b * NKV_ + kvh) * S_ * 64;
    const __half* vbase = g_v2t + (size_t)(b * NKV_ + kvh) * 64 * S_;

    // loader mapping
    const int lr  = tid >> 2;       // 0..63
    const int lsg = tid & 3;        // 16-half segment

    // ldmatrix base addresses per buffer (B-operand layout over Ks/Vt)
    const uint32_t KROW = KSP * 2;
    uint32_t kB[2], vB[2];
    #pragma unroll
    for (int u = 0; u < 2; u++) {
        kB[u] = smem_u32(&Ks[u][((lane >> 4) * 8 + (lane & 7)) * KSP + ((lane >> 3) & 1) * 8]);
        vB[u] = smem_u32(&Vt[u][((lane >> 4) * 8 + (lane & 7)) * KSP + ((lane >> 3) & 1) * 8]);
    }

    // ---- Q fragments: loop-invariant ----
    uint32_t qf[8][4];
    #pragma unroll
    for (int pc = 0; pc < 8; pc++) {
        int c = pc * 16 + tq * 2;
        qf[pc][0] = *(const uint32_t*)(qbase + (size_t)g * 128 + c);
        qf[pc][1] = *(const uint32_t*)(qbase + (size_t)(g + 8) * 128 + c);
        qf[pc][2] = *(const uint32_t*)(qbase + (size_t)g * 128 + c + 8);
        qf[pc][3] = *(const uint32_t*)(qbase + (size_t)(g + 8) * 128 + c + 8);
    }

    float m0 = -1e30f, m1 = -1e30f, l0 = 0.f, l1 = 0.f;
    float accO[8][4];
    #pragma unroll
    for (int nt = 0; nt < 8; nt++)
        #pragma unroll
        for (int c = 0; c < 4; c++) accO[nt][c] = 0.f;

    // preload tile 0 into buffer 0
    {
        const uint4* ksrc = (const uint4*)(kbase + (size_t)lr * 64 + lsg * 16);
        const uint4* vsrc = (const uint4*)(vbase + (size_t)lr * S_ + lsg * 16);
        uint4* kdst = (uint4*)(&Ks[0][lr * KSP + lsg * 16]);
        uint4* vdst = (uint4*)(&Vt[0][lr * KSP + lsg * 16]);
        kdst[0] = ksrc[0]; kdst[1] = ksrc[1];
        vdst[0] = vsrc[0]; vdst[1] = vsrc[1];
    }
    __syncthreads();

    int fb = 0;
    const int ntiles = 2 * jq + 2;
    for (int jt = 0; jt < ntiles; jt++) {
        const bool more = (jt + 1 < ntiles);
        uint4 kr0, kr1, vr0, vr1;
        if (more) {   // prefetch next KV tile
            const uint4* ksrc = (const uint4*)(kbase + (size_t)((jt + 1) * 64 + lr) * 64 + lsg * 16);
            const uint4* vsrc = (const uint4*)(vbase + (size_t)lr * S_ + (jt + 1) * 64 + lsg * 16);
            kr0 = ksrc[0]; kr1 = ksrc[1];
            vr0 = vsrc[0]; vr1 = vsrc[1];
        }

        // ---- S = (Qh+Ql) Kh ----
        float sa[8][4];
        #pragma unroll
        for (int nt = 0; nt < 8; nt++)
            #pragma unroll
            for (int c = 0; c < 4; c++) sa[nt][c] = 0.f;

        #pragma unroll
        for (int kc = 0; kc < 4; kc++) {
            uint32_t bf[8][2];
            #pragma unroll
            for (int ntp = 0; ntp < 4; ntp++)
                ldmx4(bf[2*ntp][0], bf[2*ntp][1], bf[2*ntp+1][0], bf[2*ntp+1][1],
                      kB[fb] + (uint32_t)(ntp * 16) * KROW + kc * 32);
            #pragma unroll
            for (int nt = 0; nt < 8; nt++) {
                mma16816(sa[nt], qf[kc],     bf[nt]);   // qh * kh
                mma16816(sa[nt], qf[kc + 4], bf[nt]);   // ql * kh
            }
        }

        // ---- causal mask ----
        const float NEG = -1e30f;
        if (jt >= 2 * jq) {
            int rg0 = q0 + wq * 16 + g, rg1 = rg0 + 8;
            #pragma unroll
            for (int nt = 0; nt < 8; nt++) {
                int cg = jt * 64 + nt * 8 + tq * 2;
                if (cg     > rg0) sa[nt][0] = NEG;
                if (cg + 1 > rg0) sa[nt][1] = NEG;
                if (cg     > rg1) sa[nt][2] = NEG;
                if (cg + 1 > rg1) sa[nt][3] = NEG;
            }
        }

        // ---- online softmax ----
        float rm0 = NEG, rm1 = NEG;
        #pragma unroll
        for (int nt = 0; nt < 8; nt++) {
            rm0 = fmaxf(rm0, fmaxf(sa[nt][0], sa[nt][1]));
            rm1 = fmaxf(rm1, fmaxf(sa[nt][2], sa[nt][3]));
        }
        rm0 = fmaxf(rm0, __shfl_xor_sync(0xffffffffu, rm0, 1));
        rm0 = fmaxf(rm0, __shfl_xor_sync(0xffffffffu, rm0, 2));
        rm1 = fmaxf(rm1, __shfl_xor_sync(0xffffffffu, rm1, 1));
        rm1 = fmaxf(rm1, __shfl_xor_sync(0xffffffffu, rm1, 2));

        float mn0 = fmaxf(m0, rm0), mn1 = fmaxf(m1, rm1);
        float al0 = __expf(m0 - mn0), al1 = __expf(m1 - mn1);
        m0 = mn0; m1 = mn1;

        float rs0 = 0.f, rs1 = 0.f;
        float p[8][4];
        #pragma unroll
        for (int nt = 0; nt < 8; nt++) {
            p[nt][0] = __expf(sa[nt][0] - mn0);
            p[nt][1] = __expf(sa[nt][1] - mn0);
            p[nt][2] = __expf(sa[nt][2] - mn1);
            p[nt][3] = __expf(sa[nt][3] - mn1);
            rs0 += p[nt][0] + p[nt][1];
            rs1 += p[nt][2] + p[nt][3];
        }
        rs0 += __shfl_xor_sync(0xffffffffu, rs0, 1);
        rs0 += __shfl_xor_sync(0xffffffffu, rs0, 2);
        rs1 += __shfl_xor_sync(0xffffffffu, rs1, 1);
        rs1 += __shfl_xor_sync(0xffffffffu, rs1, 2);
        l0 = l0 * al0 + rs0;
        l1 = l1 * al1 + rs1;

        #pragma unroll
        for (int nt = 0; nt < 8; nt++) {
            accO[nt][0] *= al0; accO[nt][1] *= al0;
            accO[nt][2] *= al1; accO[nt][3] *= al1;
        }

        // ---- O += (Ph+Pl) Vh ----
        #pragma unroll
        for (int vc = 0; vc < 4; vc++) {
            // P A-fragments for this k-chunk, straight from registers
            float p00 = p[2*vc][0],   p01 = p[2*vc][1];
            float p02 = p[2*vc][2],   p03 = p[2*vc][3];
            float p10 = p[2*vc+1][0], p11 = p[2*vc+1][1];
            float p12 = p[2*vc+1][2], p13 = p[2*vc+1][3];
            uint32_t aph[4], apl[4];
            aph[0] = packh(p00, p01);
            aph[1] = packh(p02, p03);
            aph[2] = packh(p10, p11);
            aph[3] = packh(p12, p13);
            apl[0] = packh(p00 - __half2float(__float2half_rn(p00)),
                           p01 - __half2float(__float2half_rn(p01)));
            apl[1] = packh(p02 - __half2float(__float2half_rn(p02)),
                           p03 - __half2float(__float2half_rn(p03)));
            apl[2] = packh(p10 - __half2float(__float2half_rn(p10)),
                           p11 - __half2float(__float2half_rn(p11)));
            apl[3] = packh(p12 - __half2float(__float2half_rn(p12)),
                           p13 - __half2float(__float2half_rn(p13)));

            uint32_t bf[8][2];
            #pragma unroll
            for (int ntp = 0; ntp < 4; ntp++)
                ldmx4(bf[2*ntp][0], bf[2*ntp][1], bf[2*ntp+1][0], bf[2*ntp+1][1],
                      vB[fb] + (uint32_t)(ntp * 16) * KROW + vc * 32);
            #pragma unroll
            for (int nt = 0; nt < 8; nt++) {
                mma16816(accO[nt], aph, bf[nt]);   // ph * vh
                mma16816(accO[nt], apl, bf[nt]);   // pl * vh
            }
        }

        if (more) {
            const int nb = fb ^ 1;   // last read one sync ago -> safe
            uint4* kdst = (uint4*)(&Ks[nb][lr * KSP + lsg * 16]);
            uint4* vdst = (uint4*)(&Vt[nb][lr * KSP + lsg * 16]);
            kdst[0] = kr0; kdst[1] = kr1;
            vdst[0] = vr0; vdst[1] = vr1;
            __syncthreads();
            fb = nb;
        }
    }

    // ---- epilogue: write O' = [hi | lo] into g_a2 ----
    float inv0 = 1.f / l0, inv1 = 1.f / l1;
    size_t r0 = (size_t)b * S_ + q0 + wq * 16 + g;
    #pragma unroll
    for (int nt = 0; nt < 8; nt++) {
        int c = h * 64 + nt * 8 + tq * 2;
        float o00 = accO[nt][0] * inv0, o01 = accO[nt][1] * inv0;
        float o10 = accO[nt][2] * inv1, o11 = accO[nt][3] * inv1;

        __half h00 = __float2half_rn(o00), h01 = __float2half_rn(o01);
        __half h10 = __float2half_rn(o10), h11 = __float2half_rn(o11);

        __half* d0 = g_a2 + r0 * KA_ + c;
        __half* d1 = g_a2 + (r0 + 8) * KA_ + c;
        *(uint32_t*)(d0)        = packh(o00, o01);
        *(uint32_t*)(d0 + 2048) = packh(o00 - __half2float(h00), o01 - __half2float(h01));
        *(uint32_t*)(d1)        = packh(o10, o11);
        *(uint32_t*)(d1 + 2048) = packh(o10 - __half2float(h10), o11 - __half2float(h11));
    }
}

// ---------------------------------------------------------------------------
// launch
// ---------------------------------------------------------------------------
extern "C" void kernel_launch(void* const* d_in, const int* in_sizes, int n_in,
                              void* d_out, int out_size)
{
    const float* X   = (const float*)d_in[0];
    const int*   pos = (const int*)  d_in[1];
    const float* Wq  = (const float*)d_in[2];
    const float* Wk  = (const float*)d_in[3];
    const float* Wv  = (const float*)d_in[4];
    const float* Wo  = (const float*)d_in[5];
    float*       out = (float*)d_out;

    void *pa2, *pwq, *pwk, *pwv, *pwo;
    cudaGetSymbolAddress(&pa2, g_a2);
    cudaGetSymbolAddress(&pwq, g_wq2);
    cudaGetSymbolAddress(&pwk, g_wk2);
    cudaGetSymbolAddress(&pwv, g_wv2);
    cudaGetSymbolAddress(&pwo, g_wo2);

    invfreq_init_kernel<<<1, 32>>>();

    cvt_hilo<<<8192, 256>>>(X, (__half*)pa2);
    cvt_w_T<<<dim3(64, 64), dim3(32, 8)>>>(Wq, (__half*)pwq, 2048);
    cvt_w_T<<<dim3(16, 64), dim3(32, 8)>>>(Wk, (__half*)pwk, 512);
    cvt_w_T<<<dim3(16, 64), dim3(32, 8)>>>(Wv, (__half*)pwv, 512);
    cvt_w_T<<<dim3(64, 64), dim3(32, 8)>>>(Wo, (__half*)pwo, 2048);

    qkv_mma<<<768, 256>>>();

    {
        const int TOT = M_ * (NH_ + NKV_) * 32;
        rope_split_kernel<<<(TOT + 255) / 256, 256>>>(pos);
    }
    cvt_v_kernel<<<dim3(64, 16, 2), dim3(32, 8)>>>();

    flash_mma<<<dim3(S_ / 128, NH_, B_), 256>>>();

    out_mma<<<512, 256>>>(out);
}

// round 12
// speedup vs baseline: 3.8384x; 1.0244x over previous
#include <cuda_runtime.h>
#include <cuda_fp16.h>
#include <math.h>
#include <cstdint>

#define B_   2
#define S_   2048
#define H_   2048
#define NH_  32
#define NKV_ 8
#define DH_  64
#define M_   (B_*S_)      // 4096 rows
#define KA_  4096         // A' k-ext: [hi | lo]
#define KW_  2048         // W stored once (hi); k-index wraps

typedef unsigned long long u64;

// ---------------------------------------------------------------------------
// Scratch (static device globals; no runtime allocation)
// ---------------------------------------------------------------------------
__device__ float g_q[(size_t)M_ * NH_ * DH_];     // fp32 QKV intermediates
__device__ float g_k[(size_t)M_ * NKV_ * DH_];
__device__ float g_v[(size_t)M_ * NKV_ * DH_];
__device__ float g_invfreq[DH_ / 2];

__device__ __align__(128) __half g_a2 [(size_t)M_   * KA_];  // X'=[hi|lo], then O'
__device__ __align__(128) __half g_wq2[(size_t)2048 * KW_];  // [N,2048] hi only
__device__ __align__(128) __half g_wk2[(size_t)512  * KW_];
__device__ __align__(128) __half g_wv2[(size_t)512  * KW_];
__device__ __align__(128) __half g_wo2[(size_t)2048 * KW_];

// split attention operands
__device__ __align__(128) __half g_q2 [(size_t)B_ * NH_  * S_ * 128]; // [qh64|ql64], pre-scaled 1/8
__device__ __align__(128) __half g_k2 [(size_t)B_ * NKV_ * S_ * 64];  // kh only
__device__ __align__(128) __half g_v2t[(size_t)B_ * NKV_ * 64 * S_];  // [d][s] vh only

// ---------------------------------------------------------------------------
// helpers
// ---------------------------------------------------------------------------
__device__ __forceinline__ void mma16816(float* d, const uint32_t* a, const uint32_t* b) {
    asm volatile("mma.sync.aligned.m16n8k16.row.col.f32.f16.f16.f32 "
                 "{%0,%1,%2,%3}, {%4,%5,%6,%7}, {%8,%9}, {%0,%1,%2,%3};"
                 : "+f"(d[0]), "+f"(d[1]), "+f"(d[2]), "+f"(d[3])
                 : "r"(a[0]), "r"(a[1]), "r"(a[2]), "r"(a[3]), "r"(b[0]), "r"(b[1]));
}
__device__ __forceinline__ uint32_t packh(float a, float b) {
    __half2 p = __halves2half2(__float2half_rn(a), __float2half_rn(b));
    return *(uint32_t*)&p;
}
__device__ __forceinline__ uint32_t smem_u32(const void* p) {
    uint32_t a;
    asm("{ .reg .u64 t; cvta.to.shared.u64 t, %1; cvt.u32.u64 %0, t; }" : "=r"(a) : "l"(p));
    return a;
}
__device__ __forceinline__ void ldmx4(uint32_t& r0, uint32_t& r1, uint32_t& r2, uint32_t& r3,
                                      uint32_t a) {
    asm volatile("ldmatrix.sync.aligned.m8n8.x4.shared.b16 {%0,%1,%2,%3}, [%4];"
                 : "=r"(r0), "=r"(r1), "=r"(r2), "=r"(r3) : "r"(a));
}
__device__ __forceinline__ void cpa16(uint32_t s, const void* g) {
    asm volatile("cp.async.ca.shared.global [%0], [%1], 16;" :: "r"(s), "l"(g));
}
#define CP_COMMIT() asm volatile("cp.async.commit_group;" ::: "memory")
#define CP_WAIT1()  asm volatile("cp.async.wait_group 1;" ::: "memory")
#define CP_WAIT0()  asm volatile("cp.async.wait_group 0;" ::: "memory")

// ---------------------------------------------------------------------------
// inv_freq init
// ---------------------------------------------------------------------------
__global__ void invfreq_init_kernel() {
    int i = threadIdx.x;
    if (i < DH_ / 2) {
        g_invfreq[i] = (float)(1.0 / pow(10000.0, (double)(2 * i) / (double)DH_));
    }
}

// ---------------------------------------------------------------------------
// hi/lo split: src fp32 [4096, 2048] -> dst f16 [4096, 4096] = [hi|lo]
// ---------------------------------------------------------------------------
__global__ __launch_bounds__(256) void cvt_hilo(const float* __restrict__ src,
                                                __half* __restrict__ dst)
{
    int t = blockIdx.x * blockDim.x + threadIdx.x;
    int m  = t >> 9;
    int c4 = (t & 511) * 4;
    float4 x = *(const float4*)(src + (size_t)m * 2048 + c4);

    __half h0 = __float2half_rn(x.x), h1 = __float2half_rn(x.y);
    __half h2 = __float2half_rn(x.z), h3 = __float2half_rn(x.w);
    __half l0 = __float2half_rn(x.x - __half2float(h0));
    __half l1 = __float2half_rn(x.y - __half2float(h1));
    __half l2 = __float2half_rn(x.z - __half2float(h2));
    __half l3 = __float2half_rn(x.w - __half2float(h3));

    __half2 H01 = __halves2half2(h0, h1), H23 = __halves2half2(h2, h3);
    __half2 L01 = __halves2half2(l0, l1), L23 = __halves2half2(l2, l3);
    uint2 Hv = make_uint2(*(uint32_t*)&H01, *(uint32_t*)&H23);
    uint2 Lv = make_uint2(*(uint32_t*)&L01, *(uint32_t*)&L23);

    size_t base = (size_t)m * KA_ + c4;
    *(uint2*)(dst + base)        = Hv;
    *(uint2*)(dst + base + 2048) = Lv;
}

// ---------------------------------------------------------------------------
// Weight transpose: W fp32 [2048, Nout] -> W' f16 [Nout, 2048] (hi only)
// ---------------------------------------------------------------------------
__global__ __launch_bounds__(256) void cvt_w_T(const float* __restrict__ W,
                                               __half* __restrict__ Wp, int Nout)
{
    __shared__ float tile[32][33];
    int tx = threadIdx.x, ty = threadIdx.y;
    int n0 = blockIdx.x * 32, k0 = blockIdx.y * 32;

    #pragma unroll
    for (int r = 0; r < 4; r++)
        tile[ty + r * 8][tx] = W[(size_t)(k0 + ty + r * 8) * Nout + n0 + tx];
    __syncthreads();

    #pragma unroll
    for (int r = 0; r < 4; r++) {
        int nl = ty + r * 8, kl = tx;
        Wp[(size_t)(n0 + nl) * KW_ + k0 + kl] = __float2half_rn(tile[kl][nl]);
    }
}

// ---------------------------------------------------------------------------
// f16 mma.sync GEMM: C = A'[M,4096] @ W'[N,2048,wrapped]^T
// 128x128 CTA tile, 8 warps (2x4), K-slab 32.
// cp.async 3-stage pipeline, ldmatrix fragment loads.
// ---------------------------------------------------------------------------
#define KSLAB 32
#define NSLAB (KA_ / KSLAB)     // 128
#define ARS   40                // smem row stride in halves (80 B)
#define BUFH  (128 * ARS)       // halves per buffer
#define GSM_BYTES (6 * BUFH * 2)   // 3 A bufs + 3 B bufs = 61440 B

__device__ __forceinline__ void mma_gemm_body(
    const __half* __restrict__ A2, const __half* __restrict__ W2,
    float* __restrict__ C, int Nout, int row0, int col0)
{
    extern __shared__ __half gsm[];
    __half* Asp = gsm;               // 3 x BUFH
    __half* Bsp = gsm + 3 * BUFH;    // 3 x BUFH

    const int tid  = threadIdx.x;
    const int lane = tid & 31;
    const int wid  = tid >> 5;
    const int wm   = wid >> 2;
    const int wn   = wid & 3;
    const int g    = lane >> 2;
    const int tq   = lane & 3;

    const int lrow = tid >> 2;
    const int lk   = (tid & 3) * 8;

    const __half* Ag = A2 + (size_t)(row0 + lrow) * KA_ + lk;
    const __half* Bg = W2 + (size_t)(col0 + lrow) * KW_ + lk;

    // per-buffer addresses
    const uint32_t AROW = ARS * 2;
    uint32_t aB[3], bB[3], aD[3], bD[3];
    #pragma unroll
    for (int u = 0; u < 3; u++) {
        aB[u] = smem_u32(Asp + u * BUFH + (wm * 64 + (lane & 15)) * ARS + (lane >> 4) * 8);
        bB[u] = smem_u32(Bsp + u * BUFH + (wn * 32 + (lane >> 4) * 8 + (lane & 7)) * ARS
                         + ((lane >> 3) & 1) * 8);
        aD[u] = smem_u32(Asp + u * BUFH + lrow * ARS + lk);
        bD[u] = smem_u32(Bsp + u * BUFH + lrow * ARS + lk);
    }

    float acc[4][4][4];
    #pragma unroll
    for (int i = 0; i < 4; i++)
        #pragma unroll
        for (int j = 0; j < 4; j++)
            #pragma unroll
            for (int c = 0; c < 4; c++) acc[i][j][c] = 0.f;

    auto issue_slab = [&](int s, int u) {
        const int ka = s * KSLAB;
        const int kw = ka & (KW_ - 1);
        cpa16(aD[u],                 Ag + ka);
        cpa16(aD[u] + 64 * AROW,     Ag + ka + (size_t)64 * KA_);
        cpa16(bD[u],                 Bg + kw);
        cpa16(bD[u] + 64 * AROW,     Bg + kw + (size_t)64 * KW_);
    };

    issue_slab(0, 0); CP_COMMIT();
    issue_slab(1, 1); CP_COMMIT();

    int buf = 0;
    for (int s = 0; s < NSLAB; s++) {
        CP_WAIT1();           // slab s resident
        __syncthreads();

        #pragma unroll
        for (int ks = 0; ks < 2; ks++) {
            uint32_t af[4][4];
            #pragma unroll
            for (int mt = 0; mt < 4; mt++)
                ldmx4(af[mt][0], af[mt][1], af[mt][2], af[mt][3],
                      aB[buf] + (uint32_t)(mt * 16) * AROW + ks * 32);
            uint32_t bf[4][2];
            ldmx4(bf[0][0], bf[0][1], bf[1][0], bf[1][1], bB[buf] + ks * 32);
            ldmx4(bf[2][0], bf[2][1], bf[3][0], bf[3][1],
                  bB[buf] + (uint32_t)16 * AROW + ks * 32);

            #pragma unroll
            for (int mt = 0; mt < 4; mt++)
                #pragma unroll
                for (int nt = 0; nt < 4; nt++)
                    mma16816(acc[mt][nt], af[mt], bf[nt]);
        }

        if (s + 2 < NSLAB) issue_slab(s + 2, (s + 2) % 3);
        CP_COMMIT();          // commit every iteration (possibly empty group)
        buf = (buf + 1) % 3;
    }

    #pragma unroll
    for (int mt = 0; mt < 4; mt++) {
        #pragma unroll
        for (int nt = 0; nt < 4; nt++) {
            int row = row0 + wm * 64 + mt * 16 + g;
            int col = col0 + wn * 32 + nt * 8 + tq * 2;
            *(float2*)&C[(size_t)row * Nout + col] =
                make_float2(acc[mt][nt][0], acc[mt][nt][1]);
            *(float2*)&C[(size_t)(row + 8) * Nout + col] =
                make_float2(acc[mt][nt][2], acc[mt][nt][3]);
        }
    }
}

__global__ __launch_bounds__(256, 2) void qkv_mma()
{
    const int bx = blockIdx.x;
    if (bx < 512)
        mma_gemm_body(g_a2, g_wq2, g_q, NH_ * DH_, (bx >> 4) * 128, (bx & 15) * 128);
    else if (bx < 640) {
        int t = bx - 512;
        mma_gemm_body(g_a2, g_wk2, g_k, NKV_ * DH_, (t >> 2) * 128, (t & 3) * 128);
    } else {
        int t = bx - 640;
        mma_gemm_body(g_a2, g_wv2, g_v, NKV_ * DH_, (t >> 2) * 128, (t & 3) * 128);
    }
}

__global__ __launch_bounds__(256, 2) void out_mma(float* __restrict__ out)
{
    const int bx = blockIdx.x;
    mma_gemm_body(g_a2, g_wo2, out, H_, (bx >> 4) * 128, (bx & 15) * 128);
}

// ---------------------------------------------------------------------------
// RoPE + split: g_q -> g_q2 [qh|ql] scaled 1/8 ; g_k -> g_k2 [kh] only
// ---------------------------------------------------------------------------
__global__ __launch_bounds__(256) void rope_split_kernel(const int* __restrict__ pos_ids)
{
    const int TOT = M_ * (NH_ + NKV_) * 32;
    int t = blockIdx.x * blockDim.x + threadIdx.x;
    if (t >= TOT) return;

    int i  = t & 31;
    int h  = (t >> 5) % (NH_ + NKV_);
    int bs = t / (32 * (NH_ + NKV_));
    int b  = bs >> 11, s = bs & 2047;

    float pos = (float)pos_ids[bs];
    float f = pos * g_invfreq[i];
    float sn, c;
    sincosf(f, &sn, &c);

    if (h < NH_) {
        const float* base = g_q + (size_t)bs * (NH_ * DH_) + h * DH_;
        __half* dst = g_q2 + ((size_t)(b * NH_ + h) * S_ + s) * 128;
        float x1 = base[i], x2 = base[i + 32];
        float o1 = (x1 * c - x2 * sn) * 0.125f;
        float o2 = (x2 * c + x1 * sn) * 0.125f;
        __half h1 = __float2half_rn(o1);
        __half h2 = __float2half_rn(o2);
        dst[i]           = h1;
        dst[i + 32]      = h2;
        dst[64 + i]      = __float2half_rn(o1 - __half2float(h1));
        dst[64 + i + 32] = __float2half_rn(o2 - __half2float(h2));
    } else {
        const float* base = g_k + (size_t)bs * (NKV_ * DH_) + (h - NH_) * DH_;
        __half* dst = g_k2 + ((size_t)(b * NKV_ + (h - NH_)) * S_ + s) * 64;
        float x1 = base[i], x2 = base[i + 32];
        dst[i]      = __float2half_rn(x1 * c - x2 * sn);
        dst[i + 32] = __float2half_rn(x2 * c + x1 * sn);
    }
}

// ---------------------------------------------------------------------------
// V transpose: g_v fp32 [m][512] -> g_v2t f16 [b][kvh][d][s] (hi only)
// ---------------------------------------------------------------------------
__global__ __launch_bounds__(256) void cvt_v_kernel()
{
    __shared__ float tile[32][33];
    int tx = threadIdx.x, ty = threadIdx.y;
    int s0 = blockIdx.x * 32;
    int cb = blockIdx.y;
    int b  = blockIdx.z;
    int kvh = cb >> 1, dbase = (cb & 1) * 32;

    #pragma unroll
    for (int r = 0; r < 4; r++)
        tile[ty + r * 8][tx] = g_v[(size_t)(b * S_ + s0 + ty + r * 8) * 512 + cb * 32 + tx];
    __syncthreads();

    #pragma unroll
    for (int r = 0; r < 4; r++) {
        int dl = ty + r * 8;
        size_t obase = ((size_t)(b * NKV_ + kvh) * 64 + dbase + dl) * S_;
        g_v2t[obase + s0 + tx] = __float2half_rn(tile[tx][dl]);
    }
}

// ---------------------------------------------------------------------------
// Flash attention on HMMA, f16 2-term splits.
// CTA: 128 q-rows x 64-kv tiles; 8 warps x 16 rows.
// ldmatrix operand loads; cp.async double-buffered K/V tiles;
// P stays in registers.
// ---------------------------------------------------------------------------
#define KSP   72                        // K/Vt smem stride (f16)

__global__ __launch_bounds__(256) void flash_mma()
{
    __shared__ __half Ks[2][64 * KSP];
    __shared__ __half Vt[2][64 * KSP];

    const int tid  = threadIdx.x;
    const int lane = tid & 31;
    const int wq   = tid >> 5;
    const int g    = lane >> 2;
    const int tq   = lane & 3;

    const int jq  = (gridDim.x - 1) - blockIdx.x;
    const int h   = blockIdx.y;
    const int b   = blockIdx.z;
    const int kvh = h >> 2;
    const int q0  = jq * 128;

    const __half* qbase = g_q2 + ((size_t)(b * NH_ + h) * S_ + q0 + wq * 16) * 128;
    const __half* kbase = g_k2 + (size_t)(b * NKV_ + kvh) * S_ * 64;
    const __half* vbase = g_v2t + (size_t)(b * NKV_ + kvh) * 64 * S_;

    const int lr  = tid >> 2;       // 0..63
    const int lsg = tid & 3;        // 16-half segment

    const uint32_t KROW = KSP * 2;
    uint32_t kB[2], vB[2], kD[2], vD[2];
    #pragma unroll
    for (int u = 0; u < 2; u++) {
        kB[u] = smem_u32(&Ks[u][((lane >> 4) * 8 + (lane & 7)) * KSP + ((lane >> 3) & 1) * 8]);
        vB[u] = smem_u32(&Vt[u][((lane >> 4) * 8 + (lane & 7)) * KSP + ((lane >> 3) & 1) * 8]);
        kD[u] = smem_u32(&Ks[u][lr * KSP + lsg * 16]);
        vD[u] = smem_u32(&Vt[u][lr * KSP + lsg * 16]);
    }

    auto issue_kv = [&](int jt, int u) {
        const __half* ks = kbase + (size_t)(jt * 64 + lr) * 64 + lsg * 16;
        const __half* vs = vbase + (size_t)lr * S_ + jt * 64 + lsg * 16;
        cpa16(kD[u],      ks);
        cpa16(kD[u] + 16, ks + 8);
        cpa16(vD[u],      vs);
        cpa16(vD[u] + 16, vs + 8);
    };

    // ---- Q fragments: loop-invariant ----
    uint32_t qf[8][4];
    #pragma unroll
    for (int pc = 0; pc < 8; pc++) {
        int c = pc * 16 + tq * 2;
        qf[pc][0] = *(const uint32_t*)(qbase + (size_t)g * 128 + c);
        qf[pc][1] = *(const uint32_t*)(qbase + (size_t)(g + 8) * 128 + c);
        qf[pc][2] = *(const uint32_t*)(qbase + (size_t)g * 128 + c + 8);
        qf[pc][3] = *(const uint32_t*)(qbase + (size_t)(g + 8) * 128 + c + 8);
    }

    float m0 = -1e30f, m1 = -1e30f, l0 = 0.f, l1 = 0.f;
    float accO[8][4];
    #pragma unroll
    for (int nt = 0; nt < 8; nt++)
        #pragma unroll
        for (int c = 0; c < 4; c++) accO[nt][c] = 0.f;

    issue_kv(0, 0); CP_COMMIT();
    CP_WAIT0();
    __syncthreads();

    int fb = 0;
    const int ntiles = 2 * jq + 2;
    for (int jt = 0; jt < ntiles; jt++) {
        const bool more = (jt + 1 < ntiles);
        if (more) { issue_kv(jt + 1, fb ^ 1); CP_COMMIT(); }

        // ---- S = (Qh+Ql) Kh ----
        float sa[8][4];
        #pragma unroll
        for (int nt = 0; nt < 8; nt++)
            #pragma unroll
            for (int c = 0; c < 4; c++) sa[nt][c] = 0.f;

        #pragma unroll
        for (int kc = 0; kc < 4; kc++) {
            uint32_t bf[8][2];
            #pragma unroll
            for (int ntp = 0; ntp < 4; ntp++)
                ldmx4(bf[2*ntp][0], bf[2*ntp][1], bf[2*ntp+1][0], bf[2*ntp+1][1],
                      kB[fb] + (uint32_t)(ntp * 16) * KROW + kc * 32);
            #pragma unroll
            for (int nt = 0; nt < 8; nt++) {
                mma16816(sa[nt], qf[kc],     bf[nt]);   // qh * kh
                mma16816(sa[nt], qf[kc + 4], bf[nt]);   // ql * kh
            }
        }

        // ---- causal mask ----
        const float NEG = -1e30f;
        if (jt >= 2 * jq) {
            int rg0 = q0 + wq * 16 + g, rg1 = rg0 + 8;
            #pragma unroll
            for (int nt = 0; nt < 8; nt++) {
                int cg = jt * 64 + nt * 8 + tq * 2;
                if (cg     > rg0) sa[nt][0] = NEG;
                if (cg + 1 > rg0) sa[nt][1] = NEG;
                if (cg     > rg1) sa[nt][2] = NEG;
                if (cg + 1 > rg1) sa[nt][3] = NEG;
            }
        }

        // ---- online softmax ----
        float rm0 = NEG, rm1 = NEG;
        #pragma unroll
        for (int nt = 0; nt < 8; nt++) {
            rm0 = fmaxf(rm0, fmaxf(sa[nt][0], sa[nt][1]));
            rm1 = fmaxf(rm1, fmaxf(sa[nt][2], sa[nt][3]));
        }
        rm0 = fmaxf(rm0, __shfl_xor_sync(0xffffffffu, rm0, 1));
        rm0 = fmaxf(rm0, __shfl_xor_sync(0xffffffffu, rm0, 2));
        rm1 = fmaxf(rm1, __shfl_xor_sync(0xffffffffu, rm1, 1));
        rm1 = fmaxf(rm1, __shfl_xor_sync(0xffffffffu, rm1, 2));

        float mn0 = fmaxf(m0, rm0), mn1 = fmaxf(m1, rm1);
        float al0 = __expf(m0 - mn0), al1 = __expf(m1 - mn1);
        m0 = mn0; m1 = mn1;

        float rs0 = 0.f, rs1 = 0.f;
        float p[8][4];
        #pragma unroll
        for (int nt = 0; nt < 8; nt++) {
            p[nt][0] = __expf(sa[nt][0] - mn0);
            p[nt][1] = __expf(sa[nt][1] - mn0);
            p[nt][2] = __expf(sa[nt][2] - mn1);
            p[nt][3] = __expf(sa[nt][3] - mn1);
            rs0 += p[nt][0] + p[nt][1];
            rs1 += p[nt][2] + p[nt][3];
        }
        rs0 += __shfl_xor_sync(0xffffffffu, rs0, 1);
        rs0 += __shfl_xor_sync(0xffffffffu, rs0, 2);
        rs1 += __shfl_xor_sync(0xffffffffu, rs1, 1);
        rs1 += __shfl_xor_sync(0xffffffffu, rs1, 2);
        l0 = l0 * al0 + rs0;
        l1 = l1 * al1 + rs1;

        #pragma unroll
        for (int nt = 0; nt < 8; nt++) {
            accO[nt][0] *= al0; accO[nt][1] *= al0;
            accO[nt][2] *= al1; accO[nt][3] *= al1;
        }

        // ---- O += (Ph+Pl) Vh ----
        #pragma unroll
        for (int vc = 0; vc < 4; vc++) {
            float p00 = p[2*vc][0],   p01 = p[2*vc][1];
            float p02 = p[2*vc][2],   p03 = p[2*vc][3];
            float p10 = p[2*vc+1][0], p11 = p[2*vc+1][1];
            float p12 = p[2*vc+1][2], p13 = p[2*vc+1][3];
            uint32_t aph[4], apl[4];
            aph[0] = packh(p00, p01);
            aph[1] = packh(p02, p03);
            aph[2] = packh(p10, p11);
            aph[3] = packh(p12, p13);
            apl[0] = packh(p00 - __half2float(__float2half_rn(p00)),
                           p01 - __half2float(__float2half_rn(p01)));
            apl[1] = packh(p02 - __half2float(__float2half_rn(p02)),
                           p03 - __half2float(__float2half_rn(p03)));
            apl[2] = packh(p10 - __half2float(__float2half_rn(p10)),
                           p11 - __half2float(__float2half_rn(p11)));
            apl[3] = packh(p12 - __half2float(__float2half_rn(p12)),
                           p13 - __half2float(__float2half_rn(p13)));

            uint32_t bf[8][2];
            #pragma unroll
            for (int ntp = 0; ntp < 4; ntp++)
                ldmx4(bf[2*ntp][0], bf[2*ntp][1], bf[2*ntp+1][0], bf[2*ntp+1][1],
                      vB[fb] + (uint32_t)(ntp * 16) * KROW + vc * 32);
            #pragma unroll
            for (int nt = 0; nt < 8; nt++) {
                mma16816(accO[nt], aph, bf[nt]);   // ph * vh
                mma16816(accO[nt], apl, bf[nt]);   // pl * vh
            }
        }

        if (more) {
            CP_WAIT0();
            __syncthreads();
            fb ^= 1;
        }
    }

    // ---- epilogue: write O' = [hi | lo] into g_a2 ----
    float inv0 = 1.f / l0, inv1 = 1.f / l1;
    size_t r0 = (size_t)b * S_ + q0 + wq * 16 + g;
    #pragma unroll
    for (int nt = 0; nt < 8; nt++) {
        int c = h * 64 + nt * 8 + tq * 2;
        float o00 = accO[nt][0] * inv0, o01 = accO[nt][1] * inv0;
        float o10 = accO[nt][2] * inv1, o11 = accO[nt][3] * inv1;

        __half h00 = __float2half_rn(o00), h01 = __float2half_rn(o01);
        __half h10 = __float2half_rn(o10), h11 = __float2half_rn(o11);

        __half* d0 = g_a2 + r0 * KA_ + c;
        __half* d1 = g_a2 + (r0 + 8) * KA_ + c;
        *(uint32_t*)(d0)        = packh(o00, o01);
        *(uint32_t*)(d0 + 2048) = packh(o00 - __half2float(h00), o01 - __half2float(h01));
        *(uint32_t*)(d1)        = packh(o10, o11);
        *(uint32_t*)(d1 + 2048) = packh(o10 - __half2float(h10), o11 - __half2float(h11));
    }
}

// ---------------------------------------------------------------------------
// launch
// ---------------------------------------------------------------------------
extern "C" void kernel_launch(void* const* d_in, const int* in_sizes, int n_in,
                              void* d_out, int out_size)
{
    const float* X   = (const float*)d_in[0];
    const int*   pos = (const int*)  d_in[1];
    const float* Wq  = (const float*)d_in[2];
    const float* Wk  = (const float*)d_in[3];
    const float* Wv  = (const float*)d_in[4];
    const float* Wo  = (const float*)d_in[5];
    float*       out = (float*)d_out;

    void *pa2, *pwq, *pwk, *pwv, *pwo;
    cudaGetSymbolAddress(&pa2, g_a2);
    cudaGetSymbolAddress(&pwq, g_wq2);
    cudaGetSymbolAddress(&pwk, g_wk2);
    cudaGetSymbolAddress(&pwv, g_wv2);
    cudaGetSymbolAddress(&pwo, g_wo2);

    cudaFuncSetAttribute(qkv_mma, cudaFuncAttributeMaxDynamicSharedMemorySize, GSM_BYTES);
    cudaFuncSetAttribute(out_mma, cudaFuncAttributeMaxDynamicSharedMemorySize, GSM_BYTES);

    invfreq_init_kernel<<<1, 32>>>();

    cvt_hilo<<<8192, 256>>>(X, (__half*)pa2);
    cvt_w_T<<<dim3(64, 64), dim3(32, 8)>>>(Wq, (__half*)pwq, 2048);
    cvt_w_T<<<dim3(16, 64), dim3(32, 8)>>>(Wk, (__half*)pwk, 512);
    cvt_w_T<<<dim3(16, 64), dim3(32, 8)>>>(Wv, (__half*)pwv, 512);
    cvt_w_T<<<dim3(64, 64), dim3(32, 8)>>>(Wo, (__half*)pwo, 2048);

    qkv_mma<<<768, 256, GSM_BYTES>>>();

    {
        const int TOT = M_ * (NH_ + NKV_) * 32;
        rope_split_kernel<<<(TOT + 255) / 256, 256>>>(pos);
    }
    cvt_v_kernel<<<dim3(64, 16, 2), dim3(32, 8)>>>();

    flash_mma<<<dim3(S_ / 128, NH_, B_), 256>>>();

    out_mma<<<512, 256, GSM_BYTES>>>(out);
}